// round 2
// baseline (speedup 1.0000x reference)
#include <cuda_runtime.h>

#define BB 8
#define CIN 64
#define NPT 2048
#define KNB 20
#define NCO 256
#define BNT (BB*NPT)          // 16384
#define RH 2560               // h region cols
#define KTOT 3904             // 2560 + 1280 + 64
#define EPS 1e-5f
#define SLOPE 0.01f

// ---------------- scratch (device globals; no allocations allowed) ----------------
static __device__ float g_xt[BNT*CIN];                     // x transposed: [bn][c]
static __device__ float g_sq[BNT];
static __device__ float g_dist[(size_t)BB*NPT*NPT];        // 128 MiB
static __device__ int   g_nbr[BNT*KNB];
static __device__ float g_W1n[12*CIN*NCO];                 // t=0..10 neighbor taps, t=11 central A1
static __device__ float g_U[(size_t)BB*12*NPT*NCO];        // 192 MiB
static __device__ float g_Wcat[NCO*KTOT];
static __device__ float g_B2[(size_t)BNT*KTOT];            // 244 MiB: [h | NB | x]
static __device__ float g_O2[BNT*NCO];
static __device__ float g_p0[256*256], g_p1[256*256], g_p2[256*256], g_p3[256*256];
static __device__ float g_sc1[NCO], g_sh1[NCO], g_sc2[NCO], g_sh2[NCO];

// ---------------- weight prep ----------------
// g_W1n[t][c][co]: t<11 -> W1[co][64+c][t]; t==11 -> A1[c][co] = sum_t(W1[co][c][t]-W1[co][64+c][t])
__global__ void k_prep_w1(const float* __restrict__ w1) {
    int gid = blockIdx.x*256 + threadIdx.x;      // 12*64*256 = 196608
    int co = gid & 255, c = (gid >> 8) & 63, t = gid >> 14;
    if (t < 11) {
        g_W1n[(t*CIN + c)*NCO + co] = w1[(co*128 + 64 + c)*11 + t];
    } else {
        float s = 0.f;
        for (int tt = 0; tt < 11; tt++)
            s += w1[(co*128 + c)*11 + tt] - w1[(co*128 + 64 + c)*11 + tt];
        g_W1n[(11*CIN + c)*NCO + co] = s;
    }
}

// g_Wcat[co2][0:2560]   = W2[co2][r/20][20 + r%20]        (inte/h part, reshape mapping)
// g_Wcat[co2][2560+i]   = W2[co2][64 + (i&63)][i>>6]       (neighbor part)
// g_Wcat[co2][3840+c]   = sum_k (W2[co2][c][k] - W2[co2][64+c][k])  (central part)
__global__ void k_prep_wcat(const float* __restrict__ w2) {
    int kp = blockIdx.x*256 + threadIdx.x;
    int co = blockIdx.y;
    if (kp >= KTOT) return;
    float val;
    if (kp < RH) {
        int c = kp / 20, kk = kp % 20;
        val = w2[(co*128 + c)*40 + 20 + kk];
    } else if (kp < RH + 1280) {
        int i = kp - RH; int k = i >> 6, c = i & 63;
        val = w2[(co*128 + 64 + c)*40 + k];
    } else {
        int c = kp - (RH + 1280);
        float s = 0.f;
        for (int k = 0; k < 20; k++)
            s += w2[(co*128 + c)*40 + k] - w2[(co*128 + 64 + c)*40 + k];
        val = s;
    }
    g_Wcat[co*KTOT + kp] = val;
}

// ---------------- stage A: transpose, norms, distances, top-k ----------------
__global__ void k_transpose(const float* __restrict__ x) {
    __shared__ float s[32][33];
    int b = blockIdx.z, n0 = blockIdx.x*32, c0 = blockIdx.y*32;
    int tx = threadIdx.x, ty = threadIdx.y;
    s[ty][tx] = x[(b*CIN + c0 + ty)*NPT + n0 + tx];
    __syncthreads();
    g_xt[(b*NPT + n0 + ty)*CIN + c0 + tx] = s[tx][ty];
}

__global__ void k_sq() {
    int bn = blockIdx.x*8 + (threadIdx.x >> 5);
    int lane = threadIdx.x & 31;
    float v0 = g_xt[bn*CIN + lane];
    float v1 = g_xt[bn*CIN + 32 + lane];
    float s = v0*v0 + v1*v1;
    for (int o = 16; o; o >>= 1) s += __shfl_down_sync(0xffffffffu, s, o);
    if (lane == 0) g_sq[bn] = s;
}

__global__ void k_dist() {
    __shared__ float sA[64][65], sB[64][65];
    int b = blockIdx.z, n0 = blockIdx.x*64, m0 = blockIdx.y*64;
    int tid = threadIdx.x;
    const float* xb = g_xt + b*NPT*CIN;
    for (int i = tid; i < 4096; i += 256) {
        int r = i >> 6, c = i & 63;
        sA[r][c] = xb[(n0 + r)*CIN + c];
        sB[r][c] = xb[(m0 + r)*CIN + c];
    }
    __syncthreads();
    int tx = tid & 15, ty = tid >> 4;
    float acc[4][4] = {};
    for (int c = 0; c < 64; c++) {
        float a[4], bb[4];
        #pragma unroll
        for (int u = 0; u < 4; u++) a[u] = sA[ty + 16*u][c];
        #pragma unroll
        for (int v = 0; v < 4; v++) bb[v] = sB[tx + 16*v][c];
        #pragma unroll
        for (int u = 0; u < 4; u++)
            #pragma unroll
            for (int v = 0; v < 4; v++) acc[u][v] += a[u]*bb[v];
    }
    size_t base = (size_t)b*NPT*NPT;
    #pragma unroll
    for (int u = 0; u < 4; u++) {
        int n = n0 + ty + 16*u;
        float sn = g_sq[b*NPT + n];
        #pragma unroll
        for (int v = 0; v < 4; v++) {
            int m = m0 + tx + 16*v;
            g_dist[base + (size_t)n*NPT + m] = sn + g_sq[b*NPT + m] - 2.f*acc[u][v];
        }
    }
}

// top-(K+1) smallest per row, ties broken by lower index (matches lax.top_k stability);
// drop the first (self), keep the next 20, in ascending-distance order.
__global__ void k_topk() {
    __shared__ float sd[NPT];
    __shared__ float rv[8]; __shared__ int ri[8];
    int bn = blockIdx.x, tid = threadIdx.x;
    const float* drow = g_dist + (size_t)bn*NPT;
    for (int i = tid; i < NPT; i += 256) sd[i] = drow[i];
    __syncthreads();
    const float INF = __int_as_float(0x7f800000);
    for (int it = 0; it <= KNB; it++) {
        float bv = INF; int bi = NPT;
        #pragma unroll
        for (int q = 0; q < 8; q++) {
            int i = tid + 256*q;
            float v = sd[i];
            if (v < bv || (v == bv && i < bi)) { bv = v; bi = i; }
        }
        for (int o = 16; o; o >>= 1) {
            float ov = __shfl_down_sync(0xffffffffu, bv, o);
            int   oi = __shfl_down_sync(0xffffffffu, bi, o);
            if (ov < bv || (ov == bv && oi < bi)) { bv = ov; bi = oi; }
        }
        if ((tid & 31) == 0) { rv[tid >> 5] = bv; ri[tid >> 5] = bi; }
        __syncthreads();
        if (tid == 0) {
            float wv = rv[0]; int wi = ri[0];
            for (int w = 1; w < 8; w++)
                if (rv[w] < wv || (rv[w] == wv && ri[w] < wi)) { wv = rv[w]; wi = ri[w]; }
            if (it > 0) g_nbr[bn*KNB + it - 1] = wi;
            sd[wi] = INF;
        }
        __syncthreads();
    }
}

// ---------------- stage B: conv1 via U-projection ----------------
// U[b][t][m][co] = sum_c W1n[t][c][co] * xt[b][m][c]   (t=11 gives central A1 term)
__global__ void k_ugemm() {
    __shared__ float sW[64][65], sX[64][65];
    int m0 = blockIdx.x*64, co0 = blockIdx.y*64;
    int z = blockIdx.z; int b = z / 12, t = z % 12;
    int tid = threadIdx.x;
    const float* xb = g_xt + b*NPT*CIN;
    const float* wt = g_W1n + t*CIN*NCO;
    for (int i = tid; i < 4096; i += 256) {
        int r = i >> 6, c = i & 63;
        sW[r][c] = wt[r*NCO + co0 + c];       // [cidx][co]
        sX[r][c] = xb[(m0 + r)*CIN + c];      // [m][cidx]
    }
    __syncthreads();
    int tx = tid & 15, ty = tid >> 4;
    float acc[4][4] = {};
    for (int c = 0; c < 64; c++) {
        float a[4], w[4];
        #pragma unroll
        for (int u = 0; u < 4; u++) a[u] = sX[ty + 16*u][c];
        #pragma unroll
        for (int v = 0; v < 4; v++) w[v] = sW[c][tx + 16*v];
        #pragma unroll
        for (int u = 0; u < 4; u++)
            #pragma unroll
            for (int v = 0; v < 4; v++) acc[u][v] += a[u]*w[v];
    }
    float* Ub = g_U + (size_t)(b*12 + t)*NPT*NCO;
    #pragma unroll
    for (int u = 0; u < 4; u++)
        #pragma unroll
        for (int v = 0; v < 4; v++)
            Ub[(m0 + ty + 16*u)*NCO + co0 + tx + 16*v] = acc[u][v];
}

// NB + central features into B2 cols [2560, 3904)
__global__ void k_gather_nbx() {
    __shared__ int si[KNB];
    int bn = blockIdx.x, tid = threadIdx.x;
    int b = bn >> 11;
    if (tid < KNB) si[tid] = g_nbr[bn*KNB + tid];
    __syncthreads();
    float* dst = g_B2 + (size_t)bn*KTOT;
    const float* xb = g_xt + b*NPT*CIN;
    for (int i = tid; i < KNB*CIN + CIN; i += 256) {
        float v; int col;
        if (i < KNB*CIN) { int k = i >> 6, c = i & 63; v = xb[si[k]*CIN + c]; col = RH + i; }
        else             { int c = i - KNB*CIN; v = g_xt[bn*CIN + c]; col = RH + 1280 + c; }
        dst[col] = v;
    }
}

// conv1 raw output: out1[co][j] = A1x[co] + sum_t U_t[idx[j+t]][co]  -> B2 cols [0,2560), r=co*10+j
__global__ void k_gather1() {
    __shared__ int si[KNB];
    int bn = blockIdx.x, co = threadIdx.x;
    int b = bn >> 11, n = bn & 2047;
    if (co < KNB) si[co] = g_nbr[bn*KNB + co];
    __syncthreads();
    const float* Ub = g_U + (size_t)b*12*NPT*NCO;
    float central = Ub[(11*NPT + n)*NCO + co];
    float acc[10];
    #pragma unroll
    for (int j = 0; j < 10; j++) acc[j] = central;
    #pragma unroll
    for (int t = 0; t < 11; t++) {
        const float* Ut = Ub + (size_t)t*NPT*NCO;
        #pragma unroll
        for (int j = 0; j < 10; j++)
            acc[j] += Ut[si[j + t]*NCO + co];
    }
    float* dst = g_B2 + (size_t)bn*KTOT + co*10;
    #pragma unroll
    for (int j = 0; j < 10; j++) dst[j] = acc[j];
}

// ---------------- BN1 stats (deterministic two-stage) + leaky ----------------
__global__ void k_stats1() {
    int sl = blockIdx.x, co = threadIdx.x;
    float s = 0.f, s2 = 0.f;
    for (int r = sl*64; r < sl*64 + 64; r++) {
        const float* p = g_B2 + (size_t)r*KTOT + co*10;
        #pragma unroll
        for (int j = 0; j < 10; j++) { float v = p[j]; s += v; s2 += v*v; }
    }
    g_p0[sl*256 + co] = s; g_p1[sl*256 + co] = s2;
}

__global__ void k_fin1(const float* __restrict__ gma, const float* __restrict__ bta) {
    int co = threadIdx.x;
    float S = 0.f, S2 = 0.f;
    for (int s = 0; s < 256; s++) { S += g_p0[s*256 + co]; S2 += g_p1[s*256 + co]; }
    const float inv = 1.f/163840.f;
    float mean = S*inv;
    float var = S2*inv - mean*mean;
    float sc = gma[co]*rsqrtf(var + EPS);
    g_sc1[co] = sc; g_sh1[co] = bta[co] - mean*sc;
}

__global__ void k_bnl1() {
    int i = blockIdx.x*256 + threadIdx.x;   // exactly BNT*RH threads
    int bn = i / RH, r = i - bn*RH;
    int co = r / 10;
    size_t a = (size_t)bn*KTOT + r;
    float v = g_B2[a];
    v = v*g_sc1[co] + g_sh1[co];
    g_B2[a] = v > 0.f ? v : SLOPE*v;
}

// ---------------- conv2 as one GEMM: O2[bn][co2] = Wcat(256x3904) . B2[bn] ----------------
__global__ void k_gemm2() {
    __shared__ float sA[16][132], sB[16][132];
    int bn0 = blockIdx.x*128, co0 = blockIdx.y*128;
    int tid = threadIdx.x, tx = tid & 15, ty = tid >> 4;
    float acc[8][8] = {};
    for (int k0 = 0; k0 < KTOT; k0 += 16) {
        __syncthreads();
        for (int i = tid; i < 2048; i += 256) {
            int r = i >> 4, c = i & 15;
            sA[c][r] = g_Wcat[(co0 + r)*KTOT + k0 + c];
            sB[c][r] = g_B2[(size_t)(bn0 + r)*KTOT + k0 + c];
        }
        __syncthreads();
        #pragma unroll
        for (int kk = 0; kk < 16; kk++) {
            float a[8], bb[8];
            #pragma unroll
            for (int u = 0; u < 8; u++) a[u] = sA[kk][ty + 16*u];
            #pragma unroll
            for (int v = 0; v < 8; v++) bb[v] = sB[kk][tx + 16*v];
            #pragma unroll
            for (int u = 0; u < 8; u++)
                #pragma unroll
                for (int v = 0; v < 8; v++) acc[u][v] += a[u]*bb[v];
        }
    }
    #pragma unroll
    for (int u = 0; u < 8; u++)
        #pragma unroll
        for (int v = 0; v < 8; v++)
            g_O2[(bn0 + tx + 16*v)*NCO + co0 + ty + 16*u] = acc[u][v];
}

// ---------------- BN2 stats + final relu/reshape ----------------
__global__ void k_stats2() {
    int sl = blockIdx.x, co = threadIdx.x;
    float s = 0.f, s2 = 0.f;
    for (int r = sl*64; r < sl*64 + 64; r++) {
        float v = g_O2[r*NCO + co]; s += v; s2 += v*v;
    }
    g_p2[sl*256 + co] = s; g_p3[sl*256 + co] = s2;
}

__global__ void k_fin2(const float* __restrict__ gma, const float* __restrict__ bta) {
    int co = threadIdx.x;
    float S = 0.f, S2 = 0.f;
    for (int s = 0; s < 256; s++) { S += g_p2[s*256 + co]; S2 += g_p3[s*256 + co]; }
    const float inv = 1.f/16384.f;
    float mean = S*inv;
    float var = S2*inv - mean*mean;
    float sc = gma[co]*rsqrtf(var + EPS);
    g_sc2[co] = sc; g_sh2[co] = bta[co] - mean*sc;
}

// y[b][c/2][(c&1)*2048 + n] = relu(bn2(O2[bn][c]))
__global__ void k_out(float* __restrict__ out) {
    __shared__ float tile[32][257];
    int bn0 = blockIdx.x*32;
    int b = bn0 >> 11, n0 = bn0 & 2047;
    int tid = threadIdx.x;
    for (int i = tid; i < 32*256; i += 256) {
        int r = i >> 8, c = i & 255;
        tile[r][c] = g_O2[(bn0 + r)*NCO + c];
    }
    __syncthreads();
    for (int i = tid; i < 8192; i += 256) {
        int f = i >> 6, w = i & 63, half = w >> 5, nn = w & 31;
        int c = 2*f + half;
        float v = tile[nn][c]*g_sc2[c] + g_sh2[c];
        v = fmaxf(v, 0.f);
        out[((size_t)b*128 + f)*4096 + half*2048 + n0 + nn] = v;
    }
}

// ---------------- launch ----------------
extern "C" void kernel_launch(void* const* d_in, const int* in_sizes, int n_in,
                              void* d_out, int out_size) {
    const float* x  = (const float*)d_in[0];
    const float* w1 = (const float*)d_in[1];
    const float* g1 = (const float*)d_in[3];
    const float* b1 = (const float*)d_in[4];
    const float* w2 = (const float*)d_in[5];
    const float* g2 = (const float*)d_in[7];
    const float* b2 = (const float*)d_in[8];
    float* out = (float*)d_out;
    // conv biases are per-channel constants and cancel exactly under BN mean-subtraction.

    k_prep_w1<<<768, 256>>>(w1);
    k_prep_wcat<<<dim3(16, 256), 256>>>(w2);
    k_transpose<<<dim3(64, 2, 8), dim3(32, 32)>>>(x);
    k_sq<<<2048, 256>>>();
    k_dist<<<dim3(32, 32, 8), 256>>>();
    k_topk<<<16384, 256>>>();
    k_ugemm<<<dim3(32, 4, 96), 256>>>();
    k_gather_nbx<<<16384, 256>>>();
    k_gather1<<<16384, 256>>>();
    k_stats1<<<256, 256>>>();
    k_fin1<<<1, 256>>>(g1, b1);
    k_bnl1<<<163840, 256>>>();
    k_gemm2<<<dim3(128, 2), 256>>>();
    k_stats2<<<256, 256>>>();
    k_fin2<<<1, 256>>>(g2, b2);
    k_out<<<512, 256>>>(out);
}

// round 4
// speedup vs baseline: 1.0414x; 1.0414x over previous
#include <cuda_runtime.h>
#include <cuda_bf16.h>
#include <cstdint>

#define BB 8
#define CIN 64
#define NPT 2048
#define KNB 20
#define NCO 256
#define BNT (BB*NPT)          // 16384
#define RH 2560               // h region cols
#define KTOT 3904             // 2560 + 1280 + 64
#define EPS 1e-5f
#define SLOPE 0.01f

// ---------------- scratch (device globals; no allocations allowed) ----------------
static __device__ float g_xt[BNT*CIN];                     // x transposed: [bn][c] fp32
static __device__ __nv_bfloat16 g_xth[BNT*CIN];            // bf16 hi
static __device__ __nv_bfloat16 g_xtl[BNT*CIN];            // bf16 lo
static __device__ float g_sq[BNT];
static __device__ float g_dist[(size_t)BB*NPT*NPT];        // 128 MiB
static __device__ int   g_nbr[BNT*KNB];
static __device__ __nv_bfloat16 g_W1h[12*NCO*CIN];         // [t][co][c] hi
static __device__ __nv_bfloat16 g_W1l[12*NCO*CIN];         // lo
static __device__ float g_U[(size_t)BB*12*NPT*NCO];        // 192 MiB
static __device__ __nv_bfloat16 g_Wch[NCO*KTOT];           // Wcat hi  [co][k]
static __device__ __nv_bfloat16 g_Wcl[NCO*KTOT];           // Wcat lo
static __device__ float g_B2[(size_t)BNT*KTOT];            // raw conv1(h) + nb + x, fp32
static __device__ __nv_bfloat16 g_B2h[(size_t)BNT*KTOT];   // post-BN/leaky, hi
static __device__ __nv_bfloat16 g_B2l[(size_t)BNT*KTOT];   // lo
static __device__ float g_O2[BNT*NCO];
static __device__ float g_p0[256*256], g_p1[256*256], g_p2[256*256], g_p3[256*256];
static __device__ float g_sc1[NCO], g_sh1[NCO], g_sc2[NCO], g_sh2[NCO];

// ---------------- helpers ----------------
__device__ __forceinline__ void split2(float x, __nv_bfloat16& h, __nv_bfloat16& l) {
    h = __float2bfloat16_rn(x);
    l = __float2bfloat16_rn(x - __bfloat162float(h));
}

__device__ __forceinline__ void mma16816(float acc[4],
    uint32_t a0, uint32_t a1, uint32_t a2, uint32_t a3, uint32_t b0, uint32_t b1) {
    asm volatile(
        "mma.sync.aligned.m16n8k16.row.col.f32.bf16.bf16.f32 "
        "{%0,%1,%2,%3},{%4,%5,%6,%7},{%8,%9},{%0,%1,%2,%3};"
        : "+f"(acc[0]), "+f"(acc[1]), "+f"(acc[2]), "+f"(acc[3])
        : "r"(a0), "r"(a1), "r"(a2), "r"(a3), "r"(b0), "r"(b1));
}

// ---------------- weight prep ----------------
// [t][co][c]: t<11 -> W1[co][64+c][t]; t==11 -> central A1 = sum_t(W1[co][c][t]-W1[co][64+c][t])
__global__ void k_prep_w1(const float* __restrict__ w1) {
    int gid = blockIdx.x*256 + threadIdx.x;      // 12*64*256 = 196608
    int co = gid & 255, c = (gid >> 8) & 63, t = gid >> 14;
    float val;
    if (t < 11) {
        val = w1[(co*128 + 64 + c)*11 + t];
    } else {
        float s = 0.f;
        for (int tt = 0; tt < 11; tt++)
            s += w1[(co*128 + c)*11 + tt] - w1[(co*128 + 64 + c)*11 + tt];
        val = s;
    }
    __nv_bfloat16 h, l; split2(val, h, l);
    g_W1h[(t*NCO + co)*CIN + c] = h;
    g_W1l[(t*NCO + co)*CIN + c] = l;
}

// Wcat[co2][0:2560] = W2[co2][r/20][20+r%20]; [2560+i] = W2[co2][64+(i&63)][i>>6];
// [3840+c] = sum_k (W2[co2][c][k] - W2[co2][64+c][k])
__global__ void k_prep_wcat(const float* __restrict__ w2) {
    int kp = blockIdx.x*256 + threadIdx.x;
    int co = blockIdx.y;
    if (kp >= KTOT) return;
    float val;
    if (kp < RH) {
        int c = kp / 20, kk = kp % 20;
        val = w2[(co*128 + c)*40 + 20 + kk];
    } else if (kp < RH + 1280) {
        int i = kp - RH; int k = i >> 6, c = i & 63;
        val = w2[(co*128 + 64 + c)*40 + k];
    } else {
        int c = kp - (RH + 1280);
        float s = 0.f;
        for (int k = 0; k < 20; k++)
            s += w2[(co*128 + c)*40 + k] - w2[(co*128 + 64 + c)*40 + k];
        val = s;
    }
    __nv_bfloat16 h, l; split2(val, h, l);
    g_Wch[co*KTOT + kp] = h;
    g_Wcl[co*KTOT + kp] = l;
}

// ---------------- stage A: transpose, norms, distances, top-k ----------------
__global__ void k_transpose(const float* __restrict__ x) {
    __shared__ float s[32][33];
    int b = blockIdx.z, n0 = blockIdx.x*32, c0 = blockIdx.y*32;
    int tx = threadIdx.x, ty = threadIdx.y;
    s[ty][tx] = x[(b*CIN + c0 + ty)*NPT + n0 + tx];
    __syncthreads();
    float v = s[tx][ty];
    int idx = (b*NPT + n0 + ty)*CIN + c0 + tx;
    g_xt[idx] = v;
    __nv_bfloat16 h, l; split2(v, h, l);
    g_xth[idx] = h; g_xtl[idx] = l;
}

__global__ void k_sq() {
    int bn = blockIdx.x*8 + (threadIdx.x >> 5);
    int lane = threadIdx.x & 31;
    float v0 = g_xt[bn*CIN + lane];
    float v1 = g_xt[bn*CIN + 32 + lane];
    float s = v0*v0 + v1*v1;
    for (int o = 16; o; o >>= 1) s += __shfl_down_sync(0xffffffffu, s, o);
    if (lane == 0) g_sq[bn] = s;
}

__global__ void k_dist() {
    __shared__ float sA[64][65], sB[64][65];
    int b = blockIdx.z, n0 = blockIdx.x*64, m0 = blockIdx.y*64;
    int tid = threadIdx.x;
    const float* xb = g_xt + b*NPT*CIN;
    for (int i = tid; i < 4096; i += 256) {
        int r = i >> 6, c = i & 63;
        sA[r][c] = xb[(n0 + r)*CIN + c];
        sB[r][c] = xb[(m0 + r)*CIN + c];
    }
    __syncthreads();
    int tx = tid & 15, ty = tid >> 4;
    float acc[4][4] = {};
    for (int c = 0; c < 64; c++) {
        float a[4], bb[4];
        #pragma unroll
        for (int u = 0; u < 4; u++) a[u] = sA[ty + 16*u][c];
        #pragma unroll
        for (int v = 0; v < 4; v++) bb[v] = sB[tx + 16*v][c];
        #pragma unroll
        for (int u = 0; u < 4; u++)
            #pragma unroll
            for (int v = 0; v < 4; v++) acc[u][v] += a[u]*bb[v];
    }
    size_t base = (size_t)b*NPT*NPT;
    #pragma unroll
    for (int u = 0; u < 4; u++) {
        int n = n0 + ty + 16*u;
        float sn = g_sq[b*NPT + n];
        #pragma unroll
        for (int v = 0; v < 4; v++) {
            int m = m0 + tx + 16*v;
            g_dist[base + (size_t)n*NPT + m] = sn + g_sq[b*NPT + m] - 2.f*acc[u][v];
        }
    }
}

__global__ void k_topk() {
    __shared__ float sd[NPT];
    __shared__ float rv[8]; __shared__ int ri[8];
    int bn = blockIdx.x, tid = threadIdx.x;
    const float* drow = g_dist + (size_t)bn*NPT;
    for (int i = tid; i < NPT; i += 256) sd[i] = drow[i];
    __syncthreads();
    const float INF = __int_as_float(0x7f800000);
    for (int it = 0; it <= KNB; it++) {
        float bv = INF; int bi = NPT;
        #pragma unroll
        for (int q = 0; q < 8; q++) {
            int i = tid + 256*q;
            float v = sd[i];
            if (v < bv || (v == bv && i < bi)) { bv = v; bi = i; }
        }
        for (int o = 16; o; o >>= 1) {
            float ov = __shfl_down_sync(0xffffffffu, bv, o);
            int   oi = __shfl_down_sync(0xffffffffu, bi, o);
            if (ov < bv || (ov == bv && oi < bi)) { bv = ov; bi = oi; }
        }
        if ((tid & 31) == 0) { rv[tid >> 5] = bv; ri[tid >> 5] = bi; }
        __syncthreads();
        if (tid == 0) {
            float wv = rv[0]; int wi = ri[0];
            for (int w = 1; w < 8; w++)
                if (rv[w] < wv || (rv[w] == wv && ri[w] < wi)) { wv = rv[w]; wi = ri[w]; }
            if (it > 0) g_nbr[bn*KNB + it - 1] = wi;
            sd[wi] = INF;
        }
        __syncthreads();
    }
}

// ---------------- conv1 U-projection via tensor cores ----------------
// U[b][t][m][co] = sum_c W1n[t][c][co] * xt[b][m][c]
// A = xt (row-major [m][c]), B = W1 ([co][c] = col-major KxN). hi/lo split, 3 MMAs.
__global__ void __launch_bounds__(256,1) k_ugemm() {
    extern __shared__ __nv_bfloat16 smu[];
    const int XS = 128*72;
    __nv_bfloat16* Xh = smu;
    __nv_bfloat16* Xl = smu + XS;
    __nv_bfloat16* Wh = smu + 2*XS;
    __nv_bfloat16* Wl = smu + 3*XS;
    int tid = threadIdx.x, lane = tid & 31, warp = tid >> 5;
    int z = blockIdx.z; int b = z / 12, t = z % 12;
    int m0 = blockIdx.x*128, co0 = blockIdx.y*128;

    const __nv_bfloat16* gxh = g_xth + (size_t)(b*NPT + m0)*CIN;
    const __nv_bfloat16* gxl = g_xtl + (size_t)(b*NPT + m0)*CIN;
    const __nv_bfloat16* gwh = g_W1h + (size_t)(t*NCO + co0)*CIN;
    const __nv_bfloat16* gwl = g_W1l + (size_t)(t*NCO + co0)*CIN;
    for (int v = tid; v < 1024; v += 256) {
        int row = v >> 3, kk = (v & 7)*8;
        int so = row*72 + kk, go = row*CIN + kk;
        *(uint4*)&Xh[so] = *(const uint4*)&gxh[go];
        *(uint4*)&Xl[so] = *(const uint4*)&gxl[go];
        *(uint4*)&Wh[so] = *(const uint4*)&gwh[go];
        *(uint4*)&Wl[so] = *(const uint4*)&gwl[go];
    }
    __syncthreads();

    int wm = (warp >> 2)*64, wn = (warp & 3)*32;
    int g = lane >> 2, t4 = lane & 3;
    float acc[4][4][4];
    #pragma unroll
    for (int i = 0; i < 4; i++)
        #pragma unroll
        for (int j = 0; j < 4; j++)
            #pragma unroll
            for (int e = 0; e < 4; e++) acc[i][j][e] = 0.f;

    #pragma unroll
    for (int kq = 0; kq < 4; kq++) {
        int kb = kq*16 + 2*t4;
        uint32_t ah[4][4], al[4][4];
        #pragma unroll
        for (int mt = 0; mt < 4; mt++) {
            int ra = (wm + mt*16 + g)*72 + kb;
            ah[mt][0] = *(uint32_t*)&Xh[ra];
            ah[mt][1] = *(uint32_t*)&Xh[ra + 8*72];
            ah[mt][2] = *(uint32_t*)&Xh[ra + 8];
            ah[mt][3] = *(uint32_t*)&Xh[ra + 8*72 + 8];
            al[mt][0] = *(uint32_t*)&Xl[ra];
            al[mt][1] = *(uint32_t*)&Xl[ra + 8*72];
            al[mt][2] = *(uint32_t*)&Xl[ra + 8];
            al[mt][3] = *(uint32_t*)&Xl[ra + 8*72 + 8];
        }
        #pragma unroll
        for (int nt = 0; nt < 4; nt++) {
            int rw = (wn + nt*8 + g)*72 + kb;
            uint32_t wh0 = *(uint32_t*)&Wh[rw], wh1 = *(uint32_t*)&Wh[rw + 8];
            uint32_t wl0 = *(uint32_t*)&Wl[rw], wl1 = *(uint32_t*)&Wl[rw + 8];
            #pragma unroll
            for (int mt = 0; mt < 4; mt++) {
                mma16816(acc[mt][nt], ah[mt][0], ah[mt][1], ah[mt][2], ah[mt][3], wh0, wh1);
                mma16816(acc[mt][nt], ah[mt][0], ah[mt][1], ah[mt][2], ah[mt][3], wl0, wl1);
                mma16816(acc[mt][nt], al[mt][0], al[mt][1], al[mt][2], al[mt][3], wh0, wh1);
            }
        }
    }

    float* Ub = g_U + (size_t)(b*12 + t)*NPT*NCO;
    #pragma unroll
    for (int mt = 0; mt < 4; mt++) {
        int row = m0 + wm + mt*16 + g;
        #pragma unroll
        for (int nt = 0; nt < 4; nt++) {
            int col = co0 + wn + nt*8 + 2*t4;
            *(float2*)&Ub[(size_t)row*NCO + col]       = make_float2(acc[mt][nt][0], acc[mt][nt][1]);
            *(float2*)&Ub[(size_t)(row + 8)*NCO + col] = make_float2(acc[mt][nt][2], acc[mt][nt][3]);
        }
    }
}

// NB + central features into B2 cols [2560, 3904)
__global__ void k_gather_nbx() {
    __shared__ int si[KNB];
    int bn = blockIdx.x, tid = threadIdx.x;
    int b = bn >> 11;
    if (tid < KNB) si[tid] = g_nbr[bn*KNB + tid];
    __syncthreads();
    float* dst = g_B2 + (size_t)bn*KTOT;
    const float* xb = g_xt + b*NPT*CIN;
    for (int i = tid; i < KNB*CIN + CIN; i += 256) {
        float v; int col;
        if (i < KNB*CIN) { int k = i >> 6, c = i & 63; v = xb[si[k]*CIN + c]; col = RH + i; }
        else             { int c = i - KNB*CIN; v = g_xt[bn*CIN + c]; col = RH + 1280 + c; }
        dst[col] = v;
    }
}

// conv1 raw output -> B2 cols [0,2560), r = co*10+j
__global__ void k_gather1() {
    __shared__ int si[KNB];
    int bn = blockIdx.x, co = threadIdx.x;
    int b = bn >> 11, n = bn & 2047;
    if (co < KNB) si[co] = g_nbr[bn*KNB + co];
    __syncthreads();
    const float* Ub = g_U + (size_t)b*12*NPT*NCO;
    float central = Ub[(11*NPT + n)*NCO + co];
    float acc[10];
    #pragma unroll
    for (int j = 0; j < 10; j++) acc[j] = central;
    #pragma unroll
    for (int t = 0; t < 11; t++) {
        const float* Ut = Ub + (size_t)t*NPT*NCO;
        #pragma unroll
        for (int j = 0; j < 10; j++)
            acc[j] += Ut[si[j + t]*NCO + co];
    }
    float* dst = g_B2 + (size_t)bn*KTOT + co*10;
    #pragma unroll
    for (int j = 0; j < 10; j++) dst[j] = acc[j];
}

// ---------------- BN1 stats ----------------
__global__ void k_stats1() {
    int sl = blockIdx.x, co = threadIdx.x;
    float s = 0.f, s2 = 0.f;
    for (int r = sl*64; r < sl*64 + 64; r++) {
        const float* p = g_B2 + (size_t)r*KTOT + co*10;
        #pragma unroll
        for (int j = 0; j < 10; j++) { float v = p[j]; s += v; s2 += v*v; }
    }
    g_p0[sl*256 + co] = s; g_p1[sl*256 + co] = s2;
}

__global__ void k_fin1(const float* __restrict__ gma, const float* __restrict__ bta) {
    int co = threadIdx.x;
    float S = 0.f, S2 = 0.f;
    for (int s = 0; s < 256; s++) { S += g_p0[s*256 + co]; S2 += g_p1[s*256 + co]; }
    const float inv = 1.f/163840.f;
    float mean = S*inv;
    float var = S2*inv - mean*mean;
    float sc = gma[co]*rsqrtf(var + EPS);
    g_sc1[co] = sc; g_sh1[co] = bta[co] - mean*sc;
}

// BN1 affine + leaky on h region, pass-through elsewhere; emit bf16 hi/lo planes
__global__ void k_split() {
    int bn = blockIdx.x;
    size_t base = (size_t)bn*KTOT;
    for (int r = threadIdx.x*4; r < KTOT; r += 1024) {
        float4 v4 = *(const float4*)&g_B2[base + r];
        float vals[4] = {v4.x, v4.y, v4.z, v4.w};
        __nv_bfloat16 h[4], l[4];
        #pragma unroll
        for (int e = 0; e < 4; e++) {
            int rr = r + e; float x = vals[e];
            if (rr < RH) {
                int co = rr / 10;
                x = x*g_sc1[co] + g_sh1[co];
                x = x > 0.f ? x : SLOPE*x;
            }
            split2(x, h[e], l[e]);
        }
        ((__nv_bfloat162*)&g_B2h[base + r])[0] = __nv_bfloat162(h[0], h[1]);
        ((__nv_bfloat162*)&g_B2h[base + r])[1] = __nv_bfloat162(h[2], h[3]);
        ((__nv_bfloat162*)&g_B2l[base + r])[0] = __nv_bfloat162(l[0], l[1]);
        ((__nv_bfloat162*)&g_B2l[base + r])[1] = __nv_bfloat162(l[2], l[3]);
    }
}

// ---------------- conv2 as one GEMM via tensor cores ----------------
// O2[bn][co] = sum_k B2'[bn][k] * Wcat[co][k]; hi/lo split, 3 MMAs.
__global__ void __launch_bounds__(256,1) k_gemm2() {
    extern __shared__ __nv_bfloat16 smg[];
    const int AS = 128*40;             // one array, elements
    // layout: buf*4*AS + arr*AS   arr: 0=Ah 1=Al 2=Wh 3=Wl
    int tid = threadIdx.x, lane = tid & 31, warp = tid >> 5;
    int bn0 = blockIdx.x*128, co0 = blockIdx.y*128;
    int wm = (warp >> 2)*64, wn = (warp & 3)*32;
    int g = lane >> 2, t4 = lane & 3;

    float acc[4][4][4];
    #pragma unroll
    for (int i = 0; i < 4; i++)
        #pragma unroll
        for (int j = 0; j < 4; j++)
            #pragma unroll
            for (int e = 0; e < 4; e++) acc[i][j][e] = 0.f;

    int r0 = tid >> 2, koff = (tid & 3)*8;
    const __nv_bfloat16* pAh = g_B2h + (size_t)(bn0 + r0)*KTOT + koff;
    const __nv_bfloat16* pAl = g_B2l + (size_t)(bn0 + r0)*KTOT + koff;
    const __nv_bfloat16* pWh = g_Wch + (size_t)(co0 + r0)*KTOT + koff;
    const __nv_bfloat16* pWl = g_Wcl + (size_t)(co0 + r0)*KTOT + koff;
    const size_t stepA = (size_t)64*KTOT;
    int so0 = r0*40 + koff, so1 = so0 + 64*40;

    const int NC = KTOT/32;            // 122 chunks
    uint4 rA[2][2], rAl[2][2], rW[2][2], rWl[2][2];

    // prologue: chunk 0 -> buf 0
    rA[0][0]  = *(const uint4*)(pAh);            rA[0][1]  = *(const uint4*)(pAh + stepA);
    rAl[0][0] = *(const uint4*)(pAl);            rAl[0][1] = *(const uint4*)(pAl + stepA);
    rW[0][0]  = *(const uint4*)(pWh);            rW[0][1]  = *(const uint4*)(pWh + stepA);
    rWl[0][0] = *(const uint4*)(pWl);            rWl[0][1] = *(const uint4*)(pWl + stepA);
    {
        __nv_bfloat16* B = smg;
        *(uint4*)&B[0*AS + so0] = rA[0][0];  *(uint4*)&B[0*AS + so1] = rA[0][1];
        *(uint4*)&B[1*AS + so0] = rAl[0][0]; *(uint4*)&B[1*AS + so1] = rAl[0][1];
        *(uint4*)&B[2*AS + so0] = rW[0][0];  *(uint4*)&B[2*AS + so1] = rW[0][1];
        *(uint4*)&B[3*AS + so0] = rWl[0][0]; *(uint4*)&B[3*AS + so1] = rWl[0][1];
    }
    __syncthreads();

    for (int c = 0; c < NC; c++) {
        int buf = c & 1;
        // prefetch chunk c+1 into registers
        if (c + 1 < NC) {
            int off = (c + 1)*32;
            rA[1][0]  = *(const uint4*)(pAh + off);          rA[1][1]  = *(const uint4*)(pAh + off + stepA);
            rAl[1][0] = *(const uint4*)(pAl + off);          rAl[1][1] = *(const uint4*)(pAl + off + stepA);
            rW[1][0]  = *(const uint4*)(pWh + off);          rW[1][1]  = *(const uint4*)(pWh + off + stepA);
            rWl[1][0] = *(const uint4*)(pWl + off);          rWl[1][1] = *(const uint4*)(pWl + off + stepA);
        }
        // compute on current buffer
        __nv_bfloat16* Ah = smg + buf*4*AS;
        __nv_bfloat16* Al = Ah + AS;
        __nv_bfloat16* Wh = Ah + 2*AS;
        __nv_bfloat16* Wl = Ah + 3*AS;
        #pragma unroll
        for (int kq = 0; kq < 2; kq++) {
            int kb = kq*16 + 2*t4;
            uint32_t ah[4][4], al[4][4];
            #pragma unroll
            for (int mt = 0; mt < 4; mt++) {
                int ra = (wm + mt*16 + g)*40 + kb;
                ah[mt][0] = *(uint32_t*)&Ah[ra];
                ah[mt][1] = *(uint32_t*)&Ah[ra + 8*40];
                ah[mt][2] = *(uint32_t*)&Ah[ra + 8];
                ah[mt][3] = *(uint32_t*)&Ah[ra + 8*40 + 8];
                al[mt][0] = *(uint32_t*)&Al[ra];
                al[mt][1] = *(uint32_t*)&Al[ra + 8*40];
                al[mt][2] = *(uint32_t*)&Al[ra + 8];
                al[mt][3] = *(uint32_t*)&Al[ra + 8*40 + 8];
            }
            #pragma unroll
            for (int nt = 0; nt < 4; nt++) {
                int rw = (wn + nt*8 + g)*40 + kb;
                uint32_t wh0 = *(uint32_t*)&Wh[rw], wh1 = *(uint32_t*)&Wh[rw + 8];
                uint32_t wl0 = *(uint32_t*)&Wl[rw], wl1 = *(uint32_t*)&Wl[rw + 8];
                #pragma unroll
                for (int mt = 0; mt < 4; mt++) {
                    mma16816(acc[mt][nt], ah[mt][0], ah[mt][1], ah[mt][2], ah[mt][3], wh0, wh1);
                    mma16816(acc[mt][nt], ah[mt][0], ah[mt][1], ah[mt][2], ah[mt][3], wl0, wl1);
                    mma16816(acc[mt][nt], al[mt][0], al[mt][1], al[mt][2], al[mt][3], wh0, wh1);
                }
            }
        }
        // store prefetched chunk into other buffer (its old data is already consumed)
        if (c + 1 < NC) {
            __nv_bfloat16* B = smg + (1 - buf)*4*AS;
            *(uint4*)&B[0*AS + so0] = rA[1][0];  *(uint4*)&B[0*AS + so1] = rA[1][1];
            *(uint4*)&B[1*AS + so0] = rAl[1][0]; *(uint4*)&B[1*AS + so1] = rAl[1][1];
            *(uint4*)&B[2*AS + so0] = rW[1][0];  *(uint4*)&B[2*AS + so1] = rW[1][1];
            *(uint4*)&B[3*AS + so0] = rWl[1][0]; *(uint4*)&B[3*AS + so1] = rWl[1][1];
        }
        __syncthreads();
    }

    #pragma unroll
    for (int mt = 0; mt < 4; mt++) {
        int row = bn0 + wm + mt*16 + g;
        #pragma unroll
        for (int nt = 0; nt < 4; nt++) {
            int col = co0 + wn + nt*8 + 2*t4;
            *(float2*)&g_O2[(size_t)row*NCO + col]       = make_float2(acc[mt][nt][0], acc[mt][nt][1]);
            *(float2*)&g_O2[(size_t)(row + 8)*NCO + col] = make_float2(acc[mt][nt][2], acc[mt][nt][3]);
        }
    }
}

// ---------------- BN2 stats + final relu/reshape ----------------
__global__ void k_stats2() {
    int sl = blockIdx.x, co = threadIdx.x;
    float s = 0.f, s2 = 0.f;
    for (int r = sl*64; r < sl*64 + 64; r++) {
        float v = g_O2[r*NCO + co]; s += v; s2 += v*v;
    }
    g_p2[sl*256 + co] = s; g_p3[sl*256 + co] = s2;
}

__global__ void k_fin2(const float* __restrict__ gma, const float* __restrict__ bta) {
    int co = threadIdx.x;
    float S = 0.f, S2 = 0.f;
    for (int s = 0; s < 256; s++) { S += g_p2[s*256 + co]; S2 += g_p3[s*256 + co]; }
    const float inv = 1.f/16384.f;
    float mean = S*inv;
    float var = S2*inv - mean*mean;
    float sc = gma[co]*rsqrtf(var + EPS);
    g_sc2[co] = sc; g_sh2[co] = bta[co] - mean*sc;
}

__global__ void k_out(float* __restrict__ out) {
    __shared__ float tile[32][257];
    int bn0 = blockIdx.x*32;
    int b = bn0 >> 11, n0 = bn0 & 2047;
    int tid = threadIdx.x;
    for (int i = tid; i < 32*256; i += 256) {
        int r = i >> 8, c = i & 255;
        tile[r][c] = g_O2[(bn0 + r)*NCO + c];
    }
    __syncthreads();
    for (int i = tid; i < 8192; i += 256) {
        int f = i >> 6, w = i & 63, half = w >> 5, nn = w & 31;
        int c = 2*f + half;
        float v = tile[nn][c]*g_sc2[c] + g_sh2[c];
        v = fmaxf(v, 0.f);
        out[((size_t)b*128 + f)*4096 + half*2048 + n0 + nn] = v;
    }
}

// ---------------- launch ----------------
extern "C" void kernel_launch(void* const* d_in, const int* in_sizes, int n_in,
                              void* d_out, int out_size) {
    const float* x  = (const float*)d_in[0];
    const float* w1 = (const float*)d_in[1];
    const float* g1 = (const float*)d_in[3];
    const float* b1 = (const float*)d_in[4];
    const float* w2 = (const float*)d_in[5];
    const float* g2 = (const float*)d_in[7];
    const float* b2 = (const float*)d_in[8];
    float* out = (float*)d_out;
    // conv biases are per-channel constants and cancel exactly under BN mean-subtraction.

    const int SM_GEMM2 = 2*4*128*40*2;   // 81920 B
    const int SM_UGEMM = 4*128*72*2;     // 73728 B
    cudaFuncSetAttribute(k_gemm2, cudaFuncAttributeMaxDynamicSharedMemorySize, SM_GEMM2);
    cudaFuncSetAttribute(k_ugemm, cudaFuncAttributeMaxDynamicSharedMemorySize, SM_UGEMM);

    k_prep_w1<<<768, 256>>>(w1);
    k_prep_wcat<<<dim3(16, 256), 256>>>(w2);
    k_transpose<<<dim3(64, 2, 8), dim3(32, 32)>>>(x);
    k_sq<<<2048, 256>>>();
    k_dist<<<dim3(32, 32, 8), 256>>>();
    k_topk<<<16384, 256>>>();
    k_ugemm<<<dim3(16, 2, 96), 256, SM_UGEMM>>>();
    k_gather_nbx<<<16384, 256>>>();
    k_gather1<<<16384, 256>>>();
    k_stats1<<<256, 256>>>();
    k_fin1<<<1, 256>>>(g1, b1);
    k_split<<<16384, 256>>>();
    k_gemm2<<<dim3(128, 2), 256, SM_GEMM2>>>();
    k_stats2<<<256, 256>>>();
    k_fin2<<<1, 256>>>(g2, b2);
    k_out<<<512, 256>>>(out);
}

// round 6
// speedup vs baseline: 2.1462x; 2.0609x over previous
#include <cuda_runtime.h>
#include <cuda_bf16.h>
#include <cstdint>

#define BB 8
#define CIN 64
#define NPT 2048
#define KNB 20
#define NCO 256
#define BNT (BB*NPT)          // 16384
#define RH 2560               // h region cols
#define KTOT 3904             // 2560 + 1280 + 64
#define EPS 1e-5f
#define SLOPE 0.01f

// ---------------- scratch (device globals; no allocations allowed) ----------------
static __device__ float g_xt[BNT*CIN];                     // x transposed: [bn][c] fp32
static __device__ __nv_bfloat16 g_xth[BNT*CIN];            // bf16 hi
static __device__ __nv_bfloat16 g_xtl[BNT*CIN];            // bf16 lo
static __device__ float g_sq[BNT];
static __device__ float g_dist[(size_t)BB*NPT*NPT];        // 128 MiB
static __device__ int   g_nbr[BNT*KNB];
static __device__ __nv_bfloat16 g_W1h[12*NCO*CIN];         // [t][co][c] hi
static __device__ __nv_bfloat16 g_W1l[12*NCO*CIN];         // lo
static __device__ float g_U[(size_t)BB*12*NPT*NCO];        // 192 MiB
static __device__ __nv_bfloat16 g_Wch[NCO*KTOT];           // Wcat hi  [co][k]
static __device__ __nv_bfloat16 g_Wcl[NCO*KTOT];           // Wcat lo
static __device__ __nv_bfloat16 g_B2h[(size_t)BNT*KTOT];   // B2 hi (raw h until bnh, then post-BN)
static __device__ __nv_bfloat16 g_B2l[(size_t)BNT*KTOT];   // lo
static __device__ float g_q0[BNT*NCO];                     // per-(bn,co) BN1 partial sum
static __device__ float g_q1[BNT*NCO];                     // per-(bn,co) BN1 partial sumsq
static __device__ float g_O2[BNT*NCO];
static __device__ float g_p0[256*256], g_p1[256*256], g_p2[256*256], g_p3[256*256];
static __device__ float g_sc1[NCO], g_sh1[NCO], g_sc2[NCO], g_sh2[NCO];

// ---------------- helpers ----------------
__device__ __forceinline__ void split2(float x, __nv_bfloat16& h, __nv_bfloat16& l) {
    h = __float2bfloat16_rn(x);
    l = __float2bfloat16_rn(x - __bfloat162float(h));
}

__device__ __forceinline__ void mma16816(float acc[4],
    uint32_t a0, uint32_t a1, uint32_t a2, uint32_t a3, uint32_t b0, uint32_t b1) {
    asm volatile(
        "mma.sync.aligned.m16n8k16.row.col.f32.bf16.bf16.f32 "
        "{%0,%1,%2,%3},{%4,%5,%6,%7},{%8,%9},{%0,%1,%2,%3};"
        : "+f"(acc[0]), "+f"(acc[1]), "+f"(acc[2]), "+f"(acc[3])
        : "r"(a0), "r"(a1), "r"(a2), "r"(a3), "r"(b0), "r"(b1));
}

// ---------------- weight prep ----------------
__global__ void k_prep_w1(const float* __restrict__ w1) {
    int gid = blockIdx.x*256 + threadIdx.x;      // 12*64*256 = 196608
    int co = gid & 255, c = (gid >> 8) & 63, t = gid >> 14;
    float val;
    if (t < 11) {
        val = w1[(co*128 + 64 + c)*11 + t];
    } else {
        float s = 0.f;
        for (int tt = 0; tt < 11; tt++)
            s += w1[(co*128 + c)*11 + tt] - w1[(co*128 + 64 + c)*11 + tt];
        val = s;
    }
    __nv_bfloat16 h, l; split2(val, h, l);
    g_W1h[(t*NCO + co)*CIN + c] = h;
    g_W1l[(t*NCO + co)*CIN + c] = l;
}

__global__ void k_prep_wcat(const float* __restrict__ w2) {
    int kp = blockIdx.x*256 + threadIdx.x;
    int co = blockIdx.y;
    if (kp >= KTOT) return;
    float val;
    if (kp < RH) {
        int c = kp / 20, kk = kp % 20;
        val = w2[(co*128 + c)*40 + 20 + kk];
    } else if (kp < RH + 1280) {
        int i = kp - RH; int k = i >> 6, c = i & 63;
        val = w2[(co*128 + 64 + c)*40 + k];
    } else {
        int c = kp - (RH + 1280);
        float s = 0.f;
        for (int k = 0; k < 20; k++)
            s += w2[(co*128 + c)*40 + k] - w2[(co*128 + 64 + c)*40 + k];
        val = s;
    }
    __nv_bfloat16 h, l; split2(val, h, l);
    g_Wch[co*KTOT + kp] = h;
    g_Wcl[co*KTOT + kp] = l;
}

// ---------------- stage A: transpose, norms, distances ----------------
__global__ void k_transpose(const float* __restrict__ x) {
    __shared__ float s[32][33];
    int b = blockIdx.z, n0 = blockIdx.x*32, c0 = blockIdx.y*32;
    int tx = threadIdx.x, ty = threadIdx.y;
    s[ty][tx] = x[(b*CIN + c0 + ty)*NPT + n0 + tx];
    __syncthreads();
    float v = s[tx][ty];
    int idx = (b*NPT + n0 + ty)*CIN + c0 + tx;
    g_xt[idx] = v;
    __nv_bfloat16 h, l; split2(v, h, l);
    g_xth[idx] = h; g_xtl[idx] = l;
}

__global__ void k_sq() {
    int bn = blockIdx.x*8 + (threadIdx.x >> 5);
    int lane = threadIdx.x & 31;
    float v0 = g_xt[bn*CIN + lane];
    float v1 = g_xt[bn*CIN + 32 + lane];
    float s = v0*v0 + v1*v1;
    for (int o = 16; o; o >>= 1) s += __shfl_down_sync(0xffffffffu, s, o);
    if (lane == 0) g_sq[bn] = s;
}

__global__ void k_dist() {
    __shared__ float sA[64][65], sB[64][65];
    int b = blockIdx.z, n0 = blockIdx.x*64, m0 = blockIdx.y*64;
    int tid = threadIdx.x;
    const float* xb = g_xt + b*NPT*CIN;
    for (int i = tid; i < 4096; i += 256) {
        int r = i >> 6, c = i & 63;
        sA[r][c] = xb[(n0 + r)*CIN + c];
        sB[r][c] = xb[(m0 + r)*CIN + c];
    }
    __syncthreads();
    int tx = tid & 15, ty = tid >> 4;
    float acc[4][4] = {};
    for (int c = 0; c < 64; c++) {
        float a[4], bb[4];
        #pragma unroll
        for (int u = 0; u < 4; u++) a[u] = sA[ty + 16*u][c];
        #pragma unroll
        for (int v = 0; v < 4; v++) bb[v] = sB[tx + 16*v][c];
        #pragma unroll
        for (int u = 0; u < 4; u++)
            #pragma unroll
            for (int v = 0; v < 4; v++) acc[u][v] += a[u]*bb[v];
    }
    size_t base = (size_t)b*NPT*NPT;
    #pragma unroll
    for (int u = 0; u < 4; u++) {
        int n = n0 + ty + 16*u;
        float sn = g_sq[b*NPT + n];
        #pragma unroll
        for (int v = 0; v < 4; v++) {
            int m = m0 + tx + 16*v;
            g_dist[base + (size_t)n*NPT + m] = sn + g_sq[b*NPT + m] - 2.f*acc[u][v];
        }
    }
}

// ---------------- top-k via exact 4-round byte radix select ----------------
// Selects the 21 smallest (dist,index) per row; writes ranks 1..20 (skip self).
__global__ void k_topk() {
    __shared__ unsigned int s_hist[256];
    __shared__ unsigned int s_kth, s_sel, s_nc;
    __shared__ unsigned long long s_cand[64];
    int bn = blockIdx.x, tid = threadIdx.x;
    const float* drow = g_dist + (size_t)bn*NPT;
    unsigned int key[8];
    #pragma unroll
    for (int q = 0; q < 8; q++) {
        unsigned int b = __float_as_uint(drow[tid + 256*q]);
        key[q] = (b & 0x80000000u) ? ~b : (b | 0x80000000u);
    }
    if (tid == 0) { s_kth = KNB + 1; s_nc = 0; }
    unsigned int prefix = 0, pmask = 0;
    #pragma unroll
    for (int round = 0; round < 4; round++) {
        int shift = 24 - 8*round;
        s_hist[tid] = 0;
        __syncthreads();
        #pragma unroll
        for (int q = 0; q < 8; q++)
            if ((key[q] & pmask) == prefix)
                atomicAdd(&s_hist[(key[q] >> shift) & 255], 1u);
        __syncthreads();
        if (tid < 32) {
            unsigned int c[8], s = 0;
            #pragma unroll
            for (int j = 0; j < 8; j++) { c[j] = s_hist[tid*8 + j]; s += c[j]; }
            unsigned int incl = s;
            #pragma unroll
            for (int o = 1; o < 32; o <<= 1) {
                unsigned int v = __shfl_up_sync(0xffffffffu, incl, o);
                if (tid >= o) incl += v;
            }
            unsigned int excl = incl - s;
            unsigned int kth = s_kth;
            if (excl < kth && incl >= kth) {
                unsigned int before = excl;
                bool done = false;
                #pragma unroll
                for (int j = 0; j < 8; j++) {
                    if (!done && before + c[j] >= kth) {
                        s_sel = tid*8 + j; s_kth = kth - before; done = true;
                    }
                    if (!done) before += c[j];
                }
            }
        }
        __syncthreads();
        prefix |= (s_sel << shift);
        pmask  |= (0xFFu << shift);
        __syncthreads();
    }
    // prefix == T = exact 21st-smallest key. Collect all key <= T.
    #pragma unroll
    for (int q = 0; q < 8; q++) {
        if (key[q] <= prefix) {
            unsigned int p = atomicAdd(&s_nc, 1u);
            if (p < 64)
                s_cand[p] = ((unsigned long long)key[q] << 32) | (unsigned int)(tid + 256*q);
        }
    }
    __syncthreads();
    int nc = s_nc; if (nc > 64) nc = 64;
    if (tid < nc) {
        unsigned long long mine = s_cand[tid];
        int rank = 0;
        for (int j = 0; j < nc; j++) rank += (s_cand[j] < mine);
        if (rank >= 1 && rank <= KNB)
            g_nbr[bn*KNB + rank - 1] = (int)(mine & 0xFFFFFFFFu);
    }
}

// ---------------- conv1 U-projection via tensor cores ----------------
__global__ void __launch_bounds__(256,1) k_ugemm() {
    extern __shared__ __nv_bfloat16 smu[];
    const int XS = 128*72;
    __nv_bfloat16* Xh = smu;
    __nv_bfloat16* Xl = smu + XS;
    __nv_bfloat16* Wh = smu + 2*XS;
    __nv_bfloat16* Wl = smu + 3*XS;
    int tid = threadIdx.x, lane = tid & 31, warp = tid >> 5;
    int z = blockIdx.z; int b = z / 12, t = z % 12;
    int m0 = blockIdx.x*128, co0 = blockIdx.y*128;

    const __nv_bfloat16* gxh = g_xth + (size_t)(b*NPT + m0)*CIN;
    const __nv_bfloat16* gxl = g_xtl + (size_t)(b*NPT + m0)*CIN;
    const __nv_bfloat16* gwh = g_W1h + (size_t)(t*NCO + co0)*CIN;
    const __nv_bfloat16* gwl = g_W1l + (size_t)(t*NCO + co0)*CIN;
    for (int v = tid; v < 1024; v += 256) {
        int row = v >> 3, kk = (v & 7)*8;
        int so = row*72 + kk, go = row*CIN + kk;
        *(uint4*)&Xh[so] = *(const uint4*)&gxh[go];
        *(uint4*)&Xl[so] = *(const uint4*)&gxl[go];
        *(uint4*)&Wh[so] = *(const uint4*)&gwh[go];
        *(uint4*)&Wl[so] = *(const uint4*)&gwl[go];
    }
    __syncthreads();

    int wm = (warp >> 2)*64, wn = (warp & 3)*32;
    int g = lane >> 2, t4 = lane & 3;
    float acc[4][4][4];
    #pragma unroll
    for (int i = 0; i < 4; i++)
        #pragma unroll
        for (int j = 0; j < 4; j++)
            #pragma unroll
            for (int e = 0; e < 4; e++) acc[i][j][e] = 0.f;

    #pragma unroll
    for (int kq = 0; kq < 4; kq++) {
        int kb = kq*16 + 2*t4;
        uint32_t ah[4][4], al[4][4];
        #pragma unroll
        for (int mt = 0; mt < 4; mt++) {
            int ra = (wm + mt*16 + g)*72 + kb;
            ah[mt][0] = *(uint32_t*)&Xh[ra];
            ah[mt][1] = *(uint32_t*)&Xh[ra + 8*72];
            ah[mt][2] = *(uint32_t*)&Xh[ra + 8];
            ah[mt][3] = *(uint32_t*)&Xh[ra + 8*72 + 8];
            al[mt][0] = *(uint32_t*)&Xl[ra];
            al[mt][1] = *(uint32_t*)&Xl[ra + 8*72];
            al[mt][2] = *(uint32_t*)&Xl[ra + 8];
            al[mt][3] = *(uint32_t*)&Xl[ra + 8*72 + 8];
        }
        #pragma unroll
        for (int nt = 0; nt < 4; nt++) {
            int rw = (wn + nt*8 + g)*72 + kb;
            uint32_t wh0 = *(uint32_t*)&Wh[rw], wh1 = *(uint32_t*)&Wh[rw + 8];
            uint32_t wl0 = *(uint32_t*)&Wl[rw], wl1 = *(uint32_t*)&Wl[rw + 8];
            #pragma unroll
            for (int mt = 0; mt < 4; mt++) {
                mma16816(acc[mt][nt], ah[mt][0], ah[mt][1], ah[mt][2], ah[mt][3], wh0, wh1);
                mma16816(acc[mt][nt], ah[mt][0], ah[mt][1], ah[mt][2], ah[mt][3], wl0, wl1);
                mma16816(acc[mt][nt], al[mt][0], al[mt][1], al[mt][2], al[mt][3], wh0, wh1);
            }
        }
    }

    float* Ub = g_U + (size_t)(b*12 + t)*NPT*NCO;
    #pragma unroll
    for (int mt = 0; mt < 4; mt++) {
        int row = m0 + wm + mt*16 + g;
        #pragma unroll
        for (int nt = 0; nt < 4; nt++) {
            int col = co0 + wn + nt*8 + 2*t4;
            *(float2*)&Ub[(size_t)row*NCO + col]       = make_float2(acc[mt][nt][0], acc[mt][nt][1]);
            *(float2*)&Ub[(size_t)(row + 8)*NCO + col] = make_float2(acc[mt][nt][2], acc[mt][nt][3]);
        }
    }
}

// NB + central features (raw, no BN) -> B2h/B2l cols [2560, 3904), copied pre-split
__global__ void k_gather_nbx() {
    __shared__ int si[KNB];
    int bn = blockIdx.x, tid = threadIdx.x;
    int b = bn >> 11;
    if (tid < KNB) si[tid] = g_nbr[bn*KNB + tid];
    __syncthreads();
    size_t base = (size_t)bn*KTOT;
    const __nv_bfloat16* xh = g_xth + (size_t)b*NPT*CIN;
    const __nv_bfloat16* xl = g_xtl + (size_t)b*NPT*CIN;
    for (int i = tid; i < KNB*CIN + CIN; i += 256) {
        __nv_bfloat16 h, l; int col;
        if (i < KNB*CIN) {
            int k = i >> 6, c = i & 63; int m = si[k];
            h = xh[m*CIN + c]; l = xl[m*CIN + c]; col = RH + i;
        } else {
            int c = i - KNB*CIN;
            h = g_xth[(size_t)bn*CIN + c]; l = g_xtl[(size_t)bn*CIN + c]; col = RH + 1280 + c;
        }
        g_B2h[base + col] = h;
        g_B2l[base + col] = l;
    }
}

// conv1 raw output -> B2h/l cols [0,2560) as bf16 hi/lo + BN1 partials per (bn,co)
__global__ void k_gather1() {
    __shared__ int si[KNB];
    int bn = blockIdx.x, co = threadIdx.x;
    int b = bn >> 11, n = bn & 2047;
    if (co < KNB) si[co] = g_nbr[bn*KNB + co];
    __syncthreads();
    const float* Ub = g_U + (size_t)b*12*NPT*NCO;
    float central = Ub[(11*NPT + n)*NCO + co];
    float acc[10];
    #pragma unroll
    for (int j = 0; j < 10; j++) acc[j] = central;
    #pragma unroll
    for (int t = 0; t < 11; t++) {
        const float* Ut = Ub + (size_t)t*NPT*NCO;
        #pragma unroll
        for (int j = 0; j < 10; j++)
            acc[j] += Ut[si[j + t]*NCO + co];
    }
    float s = 0.f, s2 = 0.f;
    size_t base = (size_t)bn*KTOT + co*10;
    #pragma unroll
    for (int j = 0; j < 10; j += 2) {
        s += acc[j] + acc[j+1];
        s2 += acc[j]*acc[j] + acc[j+1]*acc[j+1];
        __nv_bfloat16 h0, l0, h1, l1;
        split2(acc[j], h0, l0); split2(acc[j+1], h1, l1);
        *(__nv_bfloat162*)&g_B2h[base + j] = __nv_bfloat162(h0, h1);
        *(__nv_bfloat162*)&g_B2l[base + j] = __nv_bfloat162(l0, l1);
    }
    g_q0[bn*NCO + co] = s;
    g_q1[bn*NCO + co] = s2;
}

// ---------------- BN1 stats reduction (deterministic) ----------------
__global__ void k_red1() {
    int sl = blockIdx.x, co = threadIdx.x;   // 256 slices x 64 bn each
    float s = 0.f, s2 = 0.f;
    for (int r = sl*64; r < sl*64 + 64; r++) {
        s += g_q0[r*NCO + co]; s2 += g_q1[r*NCO + co];
    }
    g_p0[sl*256 + co] = s; g_p1[sl*256 + co] = s2;
}

__global__ void k_fin1(const float* __restrict__ gma, const float* __restrict__ bta) {
    int co = threadIdx.x;
    float S = 0.f, S2 = 0.f;
    for (int s = 0; s < 256; s++) { S += g_p0[s*256 + co]; S2 += g_p1[s*256 + co]; }
    const float inv = 1.f/163840.f;
    float mean = S*inv;
    float var = S2*inv - mean*mean;
    float sc = gma[co]*rsqrtf(var + EPS);
    g_sc1[co] = sc; g_sh1[co] = bta[co] - mean*sc;
}

// BN1 affine + leaky applied in-place on the bf16 hi/lo h-region
__global__ void k_bnh() {
    int bn = blockIdx.x;
    size_t base = (size_t)bn*KTOT;
    for (int r = threadIdx.x*2; r < RH; r += 512) {
        __nv_bfloat162 h2 = *(__nv_bfloat162*)&g_B2h[base + r];
        __nv_bfloat162 l2 = *(__nv_bfloat162*)&g_B2l[base + r];
        float v0 = __bfloat162float(h2.x) + __bfloat162float(l2.x);
        float v1 = __bfloat162float(h2.y) + __bfloat162float(l2.y);
        int c0 = r/10, c1 = (r+1)/10;
        v0 = v0*g_sc1[c0] + g_sh1[c0];
        v1 = v1*g_sc1[c1] + g_sh1[c1];
        v0 = v0 > 0.f ? v0 : SLOPE*v0;
        v1 = v1 > 0.f ? v1 : SLOPE*v1;
        __nv_bfloat16 h0, l0, h1, l1;
        split2(v0, h0, l0); split2(v1, h1, l1);
        *(__nv_bfloat162*)&g_B2h[base + r] = __nv_bfloat162(h0, h1);
        *(__nv_bfloat162*)&g_B2l[base + r] = __nv_bfloat162(l0, l1);
    }
}

// ---------------- conv2 as one GEMM via tensor cores ----------------
__global__ void __launch_bounds__(256,1) k_gemm2() {
    extern __shared__ __nv_bfloat16 smg[];
    const int AS = 128*40;
    int tid = threadIdx.x, lane = tid & 31, warp = tid >> 5;
    int bn0 = blockIdx.x*128, co0 = blockIdx.y*128;
    int wm = (warp >> 2)*64, wn = (warp & 3)*32;
    int g = lane >> 2, t4 = lane & 3;

    float acc[4][4][4];
    #pragma unroll
    for (int i = 0; i < 4; i++)
        #pragma unroll
        for (int j = 0; j < 4; j++)
            #pragma unroll
            for (int e = 0; e < 4; e++) acc[i][j][e] = 0.f;

    int r0 = tid >> 2, koff = (tid & 3)*8;
    const __nv_bfloat16* pAh = g_B2h + (size_t)(bn0 + r0)*KTOT + koff;
    const __nv_bfloat16* pAl = g_B2l + (size_t)(bn0 + r0)*KTOT + koff;
    const __nv_bfloat16* pWh = g_Wch + (size_t)(co0 + r0)*KTOT + koff;
    const __nv_bfloat16* pWl = g_Wcl + (size_t)(co0 + r0)*KTOT + koff;
    const size_t stepA = (size_t)64*KTOT;
    int so0 = r0*40 + koff, so1 = so0 + 64*40;

    const int NC = KTOT/32;
    uint4 rA[2][2], rAl[2][2], rW[2][2], rWl[2][2];

    rA[0][0]  = *(const uint4*)(pAh);            rA[0][1]  = *(const uint4*)(pAh + stepA);
    rAl[0][0] = *(const uint4*)(pAl);            rAl[0][1] = *(const uint4*)(pAl + stepA);
    rW[0][0]  = *(const uint4*)(pWh);            rW[0][1]  = *(const uint4*)(pWh + stepA);
    rWl[0][0] = *(const uint4*)(pWl);            rWl[0][1] = *(const uint4*)(pWl + stepA);
    {
        __nv_bfloat16* B = smg;
        *(uint4*)&B[0*AS + so0] = rA[0][0];  *(uint4*)&B[0*AS + so1] = rA[0][1];
        *(uint4*)&B[1*AS + so0] = rAl[0][0]; *(uint4*)&B[1*AS + so1] = rAl[0][1];
        *(uint4*)&B[2*AS + so0] = rW[0][0];  *(uint4*)&B[2*AS + so1] = rW[0][1];
        *(uint4*)&B[3*AS + so0] = rWl[0][0]; *(uint4*)&B[3*AS + so1] = rWl[0][1];
    }
    __syncthreads();

    for (int c = 0; c < NC; c++) {
        int buf = c & 1;
        if (c + 1 < NC) {
            int off = (c + 1)*32;
            rA[1][0]  = *(const uint4*)(pAh + off);          rA[1][1]  = *(const uint4*)(pAh + off + stepA);
            rAl[1][0] = *(const uint4*)(pAl + off);          rAl[1][1] = *(const uint4*)(pAl + off + stepA);
            rW[1][0]  = *(const uint4*)(pWh + off);          rW[1][1]  = *(const uint4*)(pWh + off + stepA);
            rWl[1][0] = *(const uint4*)(pWl + off);          rWl[1][1] = *(const uint4*)(pWl + off + stepA);
        }
        __nv_bfloat16* Ah = smg + buf*4*AS;
        __nv_bfloat16* Al = Ah + AS;
        __nv_bfloat16* Wh = Ah + 2*AS;
        __nv_bfloat16* Wl = Ah + 3*AS;
        #pragma unroll
        for (int kq = 0; kq < 2; kq++) {
            int kb = kq*16 + 2*t4;
            uint32_t ah[4][4], al[4][4];
            #pragma unroll
            for (int mt = 0; mt < 4; mt++) {
                int ra = (wm + mt*16 + g)*40 + kb;
                ah[mt][0] = *(uint32_t*)&Ah[ra];
                ah[mt][1] = *(uint32_t*)&Ah[ra + 8*40];
                ah[mt][2] = *(uint32_t*)&Ah[ra + 8];
                ah[mt][3] = *(uint32_t*)&Ah[ra + 8*40 + 8];
                al[mt][0] = *(uint32_t*)&Al[ra];
                al[mt][1] = *(uint32_t*)&Al[ra + 8*40];
                al[mt][2] = *(uint32_t*)&Al[ra + 8];
                al[mt][3] = *(uint32_t*)&Al[ra + 8*40 + 8];
            }
            #pragma unroll
            for (int nt = 0; nt < 4; nt++) {
                int rw = (wn + nt*8 + g)*40 + kb;
                uint32_t wh0 = *(uint32_t*)&Wh[rw], wh1 = *(uint32_t*)&Wh[rw + 8];
                uint32_t wl0 = *(uint32_t*)&Wl[rw], wl1 = *(uint32_t*)&Wl[rw + 8];
                #pragma unroll
                for (int mt = 0; mt < 4; mt++) {
                    mma16816(acc[mt][nt], ah[mt][0], ah[mt][1], ah[mt][2], ah[mt][3], wh0, wh1);
                    mma16816(acc[mt][nt], ah[mt][0], ah[mt][1], ah[mt][2], ah[mt][3], wl0, wl1);
                    mma16816(acc[mt][nt], al[mt][0], al[mt][1], al[mt][2], al[mt][3], wh0, wh1);
                }
            }
        }
        if (c + 1 < NC) {
            __nv_bfloat16* B = smg + (1 - buf)*4*AS;
            *(uint4*)&B[0*AS + so0] = rA[1][0];  *(uint4*)&B[0*AS + so1] = rA[1][1];
            *(uint4*)&B[1*AS + so0] = rAl[1][0]; *(uint4*)&B[1*AS + so1] = rAl[1][1];
            *(uint4*)&B[2*AS + so0] = rW[1][0];  *(uint4*)&B[2*AS + so1] = rW[1][1];
            *(uint4*)&B[3*AS + so0] = rWl[1][0]; *(uint4*)&B[3*AS + so1] = rWl[1][1];
        }
        __syncthreads();
    }

    #pragma unroll
    for (int mt = 0; mt < 4; mt++) {
        int row = bn0 + wm + mt*16 + g;
        #pragma unroll
        for (int nt = 0; nt < 4; nt++) {
            int col = co0 + wn + nt*8 + 2*t4;
            *(float2*)&g_O2[(size_t)row*NCO + col]       = make_float2(acc[mt][nt][0], acc[mt][nt][1]);
            *(float2*)&g_O2[(size_t)(row + 8)*NCO + col] = make_float2(acc[mt][nt][2], acc[mt][nt][3]);
        }
    }
}

// ---------------- BN2 stats + final relu/reshape ----------------
__global__ void k_stats2() {
    int sl = blockIdx.x, co = threadIdx.x;
    float s = 0.f, s2 = 0.f;
    for (int r = sl*64; r < sl*64 + 64; r++) {
        float v = g_O2[r*NCO + co]; s += v; s2 += v*v;
    }
    g_p2[sl*256 + co] = s; g_p3[sl*256 + co] = s2;
}

__global__ void k_fin2(const float* __restrict__ gma, const float* __restrict__ bta) {
    int co = threadIdx.x;
    float S = 0.f, S2 = 0.f;
    for (int s = 0; s < 256; s++) { S += g_p2[s*256 + co]; S2 += g_p3[s*256 + co]; }
    const float inv = 1.f/16384.f;
    float mean = S*inv;
    float var = S2*inv - mean*mean;
    float sc = gma[co]*rsqrtf(var + EPS);
    g_sc2[co] = sc; g_sh2[co] = bta[co] - mean*sc;
}

__global__ void k_out(float* __restrict__ out) {
    __shared__ float tile[32][257];
    int bn0 = blockIdx.x*32;
    int b = bn0 >> 11, n0 = bn0 & 2047;
    int tid = threadIdx.x;
    for (int i = tid; i < 32*256; i += 256) {
        int r = i >> 8, c = i & 255;
        tile[r][c] = g_O2[(bn0 + r)*NCO + c];
    }
    __syncthreads();
    for (int i = tid; i < 8192; i += 256) {
        int f = i >> 6, w = i & 63, half = w >> 5, nn = w & 31;
        int c = 2*f + half;
        float v = tile[nn][c]*g_sc2[c] + g_sh2[c];
        v = fmaxf(v, 0.f);
        out[((size_t)b*128 + f)*4096 + half*2048 + n0 + nn] = v;
    }
}

// ---------------- launch ----------------
extern "C" void kernel_launch(void* const* d_in, const int* in_sizes, int n_in,
                              void* d_out, int out_size) {
    const float* x  = (const float*)d_in[0];
    const float* w1 = (const float*)d_in[1];
    const float* g1 = (const float*)d_in[3];
    const float* b1 = (const float*)d_in[4];
    const float* w2 = (const float*)d_in[5];
    const float* g2 = (const float*)d_in[7];
    const float* b2 = (const float*)d_in[8];
    float* out = (float*)d_out;
    // conv biases are per-channel constants and cancel exactly under BN mean-subtraction.

    const int SM_GEMM2 = 2*4*128*40*2;   // 81920 B
    const int SM_UGEMM = 4*128*72*2;     // 73728 B
    cudaFuncSetAttribute(k_gemm2, cudaFuncAttributeMaxDynamicSharedMemorySize, SM_GEMM2);
    cudaFuncSetAttribute(k_ugemm, cudaFuncAttributeMaxDynamicSharedMemorySize, SM_UGEMM);

    k_prep_w1<<<768, 256>>>(w1);
    k_prep_wcat<<<dim3(16, 256), 256>>>(w2);
    k_transpose<<<dim3(64, 2, 8), dim3(32, 32)>>>(x);
    k_sq<<<2048, 256>>>();
    k_dist<<<dim3(32, 32, 8), 256>>>();
    k_topk<<<16384, 256>>>();
    k_ugemm<<<dim3(16, 2, 96), 256, SM_UGEMM>>>();
    k_gather_nbx<<<16384, 256>>>();
    k_gather1<<<16384, 256>>>();
    k_red1<<<256, 256>>>();
    k_fin1<<<1, 256>>>(g1, b1);
    k_bnh<<<16384, 256>>>();
    k_gemm2<<<dim3(128, 2), 256, SM_GEMM2>>>();
    k_stats2<<<256, 256>>>();
    k_fin2<<<1, 256>>>(g2, b2);
    k_out<<<512, 256>>>(out);
}

// round 11
// speedup vs baseline: 2.4117x; 1.1237x over previous
#include <cuda_runtime.h>
#include <cuda_bf16.h>
#include <cstdint>

#define BB 8
#define CIN 64
#define NPT 2048
#define KNB 20
#define NCO 256
#define BNT (BB*NPT)          // 16384
#define RH 2560               // h region cols
#define KTOT 3904             // 2560 + 1280 + 64
#define EPS 1e-5f
#define SLOPE 0.01f

// ---------------- scratch (device globals; no allocations allowed) ----------------
static __device__ float g_xt[BNT*CIN];                     // x transposed: [bn][c] fp32
static __device__ __nv_bfloat16 g_xth[BNT*CIN];            // bf16 hi
static __device__ __nv_bfloat16 g_xtl[BNT*CIN];            // bf16 lo
static __device__ float g_sq[BNT];
static __device__ float g_dist[(size_t)BB*NPT*NPT];        // 128 MiB
static __device__ int   g_nbr[BNT*KNB];
static __device__ __nv_bfloat16 g_W1h[12*NCO*CIN];         // [t][co][c] hi
static __device__ __nv_bfloat16 g_W1l[12*NCO*CIN];         // lo
static __device__ float g_U[(size_t)BB*12*NPT*NCO];        // 192 MiB
static __device__ __nv_bfloat16 g_Wch[NCO*KTOT];           // Wcat hi  [co][k]
static __device__ __nv_bfloat16 g_Wcl[NCO*KTOT];           // Wcat lo
static __device__ __nv_bfloat16 g_B2h[(size_t)BNT*KTOT];   // B2 hi
static __device__ __nv_bfloat16 g_B2l[(size_t)BNT*KTOT];   // lo
static __device__ float g_q0[BNT*NCO];                     // per-(bn,co) BN1 partial sum
static __device__ float g_q1[BNT*NCO];                     // per-(bn,co) BN1 partial sumsq
static __device__ float g_O2[BNT*NCO];
static __device__ float g_p0[256*256], g_p1[256*256], g_p2[256*256], g_p3[256*256];
static __device__ float g_sc1[NCO], g_sh1[NCO], g_sc2[NCO], g_sh2[NCO];

// ---------------- helpers ----------------
__device__ __forceinline__ void split2(float x, __nv_bfloat16& h, __nv_bfloat16& l) {
    h = __float2bfloat16_rn(x);
    l = __float2bfloat16_rn(x - __bfloat162float(h));
}

__device__ __forceinline__ void mma16816(float acc[4],
    const uint32_t a[4], uint32_t b0, uint32_t b1) {
    asm volatile(
        "mma.sync.aligned.m16n8k16.row.col.f32.bf16.bf16.f32 "
        "{%0,%1,%2,%3},{%4,%5,%6,%7},{%8,%9},{%0,%1,%2,%3};"
        : "+f"(acc[0]), "+f"(acc[1]), "+f"(acc[2]), "+f"(acc[3])
        : "r"(a[0]), "r"(a[1]), "r"(a[2]), "r"(a[3]), "r"(b0), "r"(b1));
}

__device__ __forceinline__ void ldsm4(uint32_t r[4], uint32_t saddr) {
    asm volatile("ldmatrix.sync.aligned.m8n8.x4.shared.b16 {%0,%1,%2,%3}, [%4];"
        : "=r"(r[0]), "=r"(r[1]), "=r"(r[2]), "=r"(r[3]) : "r"(saddr));
}

// ---------------- weight prep ----------------
__global__ void k_prep_w1(const float* __restrict__ w1) {
    int gid = blockIdx.x*256 + threadIdx.x;      // 12*64*256 = 196608
    int co = gid & 255, c = (gid >> 8) & 63, t = gid >> 14;
    float val;
    if (t < 11) {
        val = w1[(co*128 + 64 + c)*11 + t];
    } else {
        float s = 0.f;
        for (int tt = 0; tt < 11; tt++)
            s += w1[(co*128 + c)*11 + tt] - w1[(co*128 + 64 + c)*11 + tt];
        val = s;
    }
    __nv_bfloat16 h, l; split2(val, h, l);
    g_W1h[(t*NCO + co)*CIN + c] = h;
    g_W1l[(t*NCO + co)*CIN + c] = l;
}

__global__ void k_prep_wcat(const float* __restrict__ w2) {
    int kp = blockIdx.x*256 + threadIdx.x;
    int co = blockIdx.y;
    if (kp >= KTOT) return;
    float val;
    if (kp < RH) {
        int c = kp / 20, kk = kp % 20;
        val = w2[(co*128 + c)*40 + 20 + kk];
    } else if (kp < RH + 1280) {
        int i = kp - RH; int k = i >> 6, c = i & 63;
        val = w2[(co*128 + 64 + c)*40 + k];
    } else {
        int c = kp - (RH + 1280);
        float s = 0.f;
        for (int k = 0; k < 20; k++)
            s += w2[(co*128 + c)*40 + k] - w2[(co*128 + 64 + c)*40 + k];
        val = s;
    }
    __nv_bfloat16 h, l; split2(val, h, l);
    g_Wch[co*KTOT + kp] = h;
    g_Wcl[co*KTOT + kp] = l;
}

// ---------------- stage A: transpose, norms, distances (triangular), top-k ----------------
__global__ void k_transpose(const float* __restrict__ x) {
    __shared__ float s[32][33];
    int b = blockIdx.z, n0 = blockIdx.x*32, c0 = blockIdx.y*32;
    int tx = threadIdx.x, ty = threadIdx.y;
    s[ty][tx] = x[(b*CIN + c0 + ty)*NPT + n0 + tx];
    __syncthreads();
    float v = s[tx][ty];
    int idx = (b*NPT + n0 + ty)*CIN + c0 + tx;
    g_xt[idx] = v;
    __nv_bfloat16 h, l; split2(v, h, l);
    g_xth[idx] = h; g_xtl[idx] = l;
}

// norms via shuffle-tree reduction — numerics MUST match the round-6 passing kernel
// (serial in-tile norms perturb distances enough to flip near-tie kNN ranks vs jax).
__global__ void k_sq() {
    int bn = blockIdx.x*8 + (threadIdx.x >> 5);
    int lane = threadIdx.x & 31;
    float v0 = g_xt[bn*CIN + lane];
    float v1 = g_xt[bn*CIN + 32 + lane];
    float s = v0*v0 + v1*v1;
    for (int o = 16; o; o >>= 1) s += __shfl_down_sync(0xffffffffu, s, o);
    if (lane == 0) g_sq[bn] = s;
}

// triangular tile (i<=j); mirrors tile to [m][n] via smem stage; norms from g_sq
__global__ void k_dist() {
    __shared__ float sA[64][65], sB[64][65];
    __shared__ float s_n[64], s_m[64];
    int b = blockIdx.y;
    int L = blockIdx.x;
    int i = 0, rem = L;
    while (rem >= 32 - i) { rem -= 32 - i; i++; }
    int j = i + rem;
    int n0 = i*64, m0 = j*64;
    int tid = threadIdx.x;
    const float* xb = g_xt + (size_t)b*NPT*CIN;
    for (int v = tid; v < 4096; v += 256) {
        int r = v >> 6, c = v & 63;
        sA[r][c] = xb[(n0 + r)*CIN + c];
        sB[r][c] = xb[(m0 + r)*CIN + c];
    }
    if (tid < 128) {
        int r = tid & 63;
        if (tid < 64) s_n[r] = g_sq[b*NPT + n0 + r];
        else          s_m[r] = g_sq[b*NPT + m0 + r];
    }
    __syncthreads();
    int tx = tid & 15, ty = tid >> 4;
    float acc[4][4] = {};
    for (int c = 0; c < 64; c++) {
        float a[4], bb[4];
        #pragma unroll
        for (int u = 0; u < 4; u++) a[u] = sA[ty + 16*u][c];
        #pragma unroll
        for (int v = 0; v < 4; v++) bb[v] = sB[tx + 16*v][c];
        #pragma unroll
        for (int u = 0; u < 4; u++)
            #pragma unroll
            for (int v = 0; v < 4; v++) acc[u][v] += a[u]*bb[v];
    }
    size_t base = (size_t)b*NPT*NPT;
    float val[4][4];
    #pragma unroll
    for (int u = 0; u < 4; u++) {
        float sn = s_n[ty + 16*u];
        #pragma unroll
        for (int v = 0; v < 4; v++)
            val[u][v] = sn + s_m[tx + 16*v] - 2.f*acc[u][v];
    }
    #pragma unroll
    for (int u = 0; u < 4; u++) {
        int n = n0 + ty + 16*u;
        #pragma unroll
        for (int v = 0; v < 4; v++)
            g_dist[base + (size_t)n*NPT + m0 + tx + 16*v] = val[u][v];
    }
    if (i != j) {
        __syncthreads();
        #pragma unroll
        for (int u = 0; u < 4; u++)
            #pragma unroll
            for (int v = 0; v < 4; v++)
                sA[tx + 16*v][ty + 16*u] = val[u][v];
        __syncthreads();
        for (int idx2 = tid; idx2 < 4096; idx2 += 256) {
            int r = idx2 >> 6, c = idx2 & 63;
            g_dist[base + (size_t)(m0 + r)*NPT + n0 + c] = sA[r][c];
        }
    }
}

// ---------------- top-k via exact 4-round byte radix select ----------------
__global__ void k_topk() {
    __shared__ unsigned int s_hist[256];
    __shared__ unsigned int s_kth, s_sel, s_nc;
    __shared__ unsigned long long s_cand[64];
    int bn = blockIdx.x, tid = threadIdx.x;
    const float* drow = g_dist + (size_t)bn*NPT;
    unsigned int key[8];
    #pragma unroll
    for (int q = 0; q < 8; q++) {
        unsigned int b = __float_as_uint(drow[tid + 256*q]);
        key[q] = (b & 0x80000000u) ? ~b : (b | 0x80000000u);
    }
    if (tid == 0) { s_kth = KNB + 1; s_nc = 0; }
    unsigned int prefix = 0, pmask = 0;
    #pragma unroll
    for (int round = 0; round < 4; round++) {
        int shift = 24 - 8*round;
        s_hist[tid] = 0;
        __syncthreads();
        #pragma unroll
        for (int q = 0; q < 8; q++)
            if ((key[q] & pmask) == prefix)
                atomicAdd(&s_hist[(key[q] >> shift) & 255], 1u);
        __syncthreads();
        if (tid < 32) {
            unsigned int c[8], s = 0;
            #pragma unroll
            for (int jj = 0; jj < 8; jj++) { c[jj] = s_hist[tid*8 + jj]; s += c[jj]; }
            unsigned int incl = s;
            #pragma unroll
            for (int o = 1; o < 32; o <<= 1) {
                unsigned int v = __shfl_up_sync(0xffffffffu, incl, o);
                if (tid >= o) incl += v;
            }
            unsigned int excl = incl - s;
            unsigned int kth = s_kth;
            if (excl < kth && incl >= kth) {
                unsigned int before = excl;
                bool done = false;
                #pragma unroll
                for (int jj = 0; jj < 8; jj++) {
                    if (!done && before + c[jj] >= kth) {
                        s_sel = tid*8 + jj; s_kth = kth - before; done = true;
                    }
                    if (!done) before += c[jj];
                }
            }
        }
        __syncthreads();
        prefix |= (s_sel << shift);
        pmask  |= (0xFFu << shift);
        __syncthreads();
    }
    #pragma unroll
    for (int q = 0; q < 8; q++) {
        if (key[q] <= prefix) {
            unsigned int p = atomicAdd(&s_nc, 1u);
            if (p < 64)
                s_cand[p] = ((unsigned long long)key[q] << 32) | (unsigned int)(tid + 256*q);
        }
    }
    __syncthreads();
    int nc = s_nc; if (nc > 64) nc = 64;
    if (tid < nc) {
        unsigned long long mine = s_cand[tid];
        int rank = 0;
        for (int jj = 0; jj < nc; jj++) rank += (s_cand[jj] < mine);
        if (rank >= 1 && rank <= KNB)
            g_nbr[bn*KNB + rank - 1] = (int)(mine & 0xFFFFFFFFu);
    }
}

// ---------------- conv1 U-projection via tensor cores (ldmatrix) ----------------
__global__ void __launch_bounds__(256,1) k_ugemm() {
    extern __shared__ __nv_bfloat16 smu[];
    const int XS = 128*72;                 // elements per plane
    const uint32_t XS2 = XS*2;             // bytes
    int tid = threadIdx.x, lane = tid & 31, warp = tid >> 5;
    int z = blockIdx.z; int b = z / 12, t = z % 12;
    int m0 = blockIdx.x*128, co0 = blockIdx.y*128;

    const __nv_bfloat16* gxh = g_xth + (size_t)(b*NPT + m0)*CIN;
    const __nv_bfloat16* gxl = g_xtl + (size_t)(b*NPT + m0)*CIN;
    const __nv_bfloat16* gwh = g_W1h + (size_t)(t*NCO + co0)*CIN;
    const __nv_bfloat16* gwl = g_W1l + (size_t)(t*NCO + co0)*CIN;
    for (int v = tid; v < 1024; v += 256) {
        int row = v >> 3, kk = (v & 7)*8;
        int so = row*72 + kk, go = row*CIN + kk;
        *(uint4*)&smu[0*XS + so] = *(const uint4*)&gxh[go];
        *(uint4*)&smu[1*XS + so] = *(const uint4*)&gxl[go];
        *(uint4*)&smu[2*XS + so] = *(const uint4*)&gwh[go];
        *(uint4*)&smu[3*XS + so] = *(const uint4*)&gwl[go];
    }
    __syncthreads();

    int wm = (warp >> 2)*64, wn = (warp & 3)*32;
    int g = lane >> 2, t4 = lane & 3;
    uint32_t sb = (uint32_t)__cvta_generic_to_shared(smu);
    int aRow = (lane & 7) + ((lane >> 3) & 1)*8;
    int aCol = (lane >> 4)*8;
    uint32_t aoff = ((wm + aRow)*72 + aCol)*2;
    int bRow = (lane & 7) + ((lane >> 4) & 1)*8;
    int bCol = ((lane >> 3) & 1)*8;
    uint32_t boff = ((wn + bRow)*72 + bCol)*2;

    float acc[4][4][4];
    #pragma unroll
    for (int i = 0; i < 4; i++)
        #pragma unroll
        for (int j = 0; j < 4; j++)
            #pragma unroll
            for (int e = 0; e < 4; e++) acc[i][j][e] = 0.f;

    #pragma unroll
    for (int kq = 0; kq < 4; kq++) {
        uint32_t ah[4][4], al[4][4];
        #pragma unroll
        for (int mt = 0; mt < 4; mt++) {
            ldsm4(ah[mt], sb + 0*XS2 + aoff + mt*2304 + kq*32);
            ldsm4(al[mt], sb + 1*XS2 + aoff + mt*2304 + kq*32);
        }
        #pragma unroll
        for (int p = 0; p < 2; p++) {
            uint32_t bh[4], bl[4];
            ldsm4(bh, sb + 2*XS2 + boff + p*2304 + kq*32);
            ldsm4(bl, sb + 3*XS2 + boff + p*2304 + kq*32);
            #pragma unroll
            for (int mt = 0; mt < 4; mt++) {
                mma16816(acc[mt][2*p],   ah[mt], bh[0], bh[1]);
                mma16816(acc[mt][2*p],   ah[mt], bl[0], bl[1]);
                mma16816(acc[mt][2*p],   al[mt], bh[0], bh[1]);
                mma16816(acc[mt][2*p+1], ah[mt], bh[2], bh[3]);
                mma16816(acc[mt][2*p+1], ah[mt], bl[2], bl[3]);
                mma16816(acc[mt][2*p+1], al[mt], bh[2], bh[3]);
            }
        }
    }

    float* Ub = g_U + (size_t)(b*12 + t)*NPT*NCO;
    #pragma unroll
    for (int mt = 0; mt < 4; mt++) {
        int row = m0 + wm + mt*16 + g;
        #pragma unroll
        for (int nt = 0; nt < 4; nt++) {
            int col = co0 + wn + nt*8 + 2*t4;
            *(float2*)&Ub[(size_t)row*NCO + col]       = make_float2(acc[mt][nt][0], acc[mt][nt][1]);
            *(float2*)&Ub[(size_t)(row + 8)*NCO + col] = make_float2(acc[mt][nt][2], acc[mt][nt][3]);
        }
    }
}

// NB + central features (raw) -> B2h/B2l cols [2560, 3904)
__global__ void k_gather_nbx() {
    __shared__ int si[KNB];
    int bn = blockIdx.x, tid = threadIdx.x;
    int b = bn >> 11;
    if (tid < KNB) si[tid] = g_nbr[bn*KNB + tid];
    __syncthreads();
    size_t base = (size_t)bn*KTOT;
    const __nv_bfloat16* xh = g_xth + (size_t)b*NPT*CIN;
    const __nv_bfloat16* xl = g_xtl + (size_t)b*NPT*CIN;
    for (int i = tid; i < KNB*CIN + CIN; i += 256) {
        __nv_bfloat16 h, l; int col;
        if (i < KNB*CIN) {
            int k = i >> 6, c = i & 63; int m = si[k];
            h = xh[m*CIN + c]; l = xl[m*CIN + c]; col = RH + i;
        } else {
            int c = i - KNB*CIN;
            h = g_xth[(size_t)bn*CIN + c]; l = g_xtl[(size_t)bn*CIN + c]; col = RH + 1280 + c;
        }
        g_B2h[base + col] = h;
        g_B2l[base + col] = l;
    }
}

// conv1 raw output -> B2h/l cols [0,2560) + BN1 partials per (bn,co)
__global__ void k_gather1() {
    __shared__ int si[KNB];
    int bn = blockIdx.x, co = threadIdx.x;
    int b = bn >> 11, n = bn & 2047;
    if (co < KNB) si[co] = g_nbr[bn*KNB + co];
    __syncthreads();
    const float* Ub = g_U + (size_t)b*12*NPT*NCO;
    float central = Ub[(11*NPT + n)*NCO + co];
    float acc[10];
    #pragma unroll
    for (int j = 0; j < 10; j++) acc[j] = central;
    #pragma unroll
    for (int t = 0; t < 11; t++) {
        const float* Ut = Ub + (size_t)t*NPT*NCO;
        #pragma unroll
        for (int j = 0; j < 10; j++)
            acc[j] += Ut[si[j + t]*NCO + co];
    }
    float s = 0.f, s2 = 0.f;
    size_t base = (size_t)bn*KTOT + co*10;
    #pragma unroll
    for (int j = 0; j < 10; j += 2) {
        s += acc[j] + acc[j+1];
        s2 += acc[j]*acc[j] + acc[j+1]*acc[j+1];
        __nv_bfloat16 h0, l0, h1, l1;
        split2(acc[j], h0, l0); split2(acc[j+1], h1, l1);
        *(__nv_bfloat162*)&g_B2h[base + j] = __nv_bfloat162(h0, h1);
        *(__nv_bfloat162*)&g_B2l[base + j] = __nv_bfloat162(l0, l1);
    }
    g_q0[bn*NCO + co] = s;
    g_q1[bn*NCO + co] = s2;
}

// ---------------- BN1 stats reduction ----------------
__global__ void k_red1() {
    int sl = blockIdx.x, co = threadIdx.x;
    float s = 0.f, s2 = 0.f;
    for (int r = sl*64; r < sl*64 + 64; r++) {
        s += g_q0[r*NCO + co]; s2 += g_q1[r*NCO + co];
    }
    g_p0[sl*256 + co] = s; g_p1[sl*256 + co] = s2;
}

__global__ void k_fin1(const float* __restrict__ gma, const float* __restrict__ bta) {
    int co = threadIdx.x;
    float S = 0.f, S2 = 0.f;
    for (int s = 0; s < 256; s++) { S += g_p0[s*256 + co]; S2 += g_p1[s*256 + co]; }
    const float inv = 1.f/163840.f;
    float mean = S*inv;
    float var = S2*inv - mean*mean;
    float sc = gma[co]*rsqrtf(var + EPS);
    g_sc1[co] = sc; g_sh1[co] = bta[co] - mean*sc;
}

// BN1 affine + leaky in-place on bf16 hi/lo h-region
__global__ void k_bnh() {
    int bn = blockIdx.x;
    size_t base = (size_t)bn*KTOT;
    for (int r = threadIdx.x*2; r < RH; r += 512) {
        __nv_bfloat162 h2 = *(__nv_bfloat162*)&g_B2h[base + r];
        __nv_bfloat162 l2 = *(__nv_bfloat162*)&g_B2l[base + r];
        float v0 = __bfloat162float(h2.x) + __bfloat162float(l2.x);
        float v1 = __bfloat162float(h2.y) + __bfloat162float(l2.y);
        int c0 = r/10, c1 = (r+1)/10;
        v0 = v0*g_sc1[c0] + g_sh1[c0];
        v1 = v1*g_sc1[c1] + g_sh1[c1];
        v0 = v0 > 0.f ? v0 : SLOPE*v0;
        v1 = v1 > 0.f ? v1 : SLOPE*v1;
        __nv_bfloat16 h0, l0, h1, l1;
        split2(v0, h0, l0); split2(v1, h1, l1);
        *(__nv_bfloat162*)&g_B2h[base + r] = __nv_bfloat162(h0, h1);
        *(__nv_bfloat162*)&g_B2l[base + r] = __nv_bfloat162(l0, l1);
    }
}

// ---------------- conv2 as one GEMM via tensor cores (ldmatrix) ----------------
__global__ void __launch_bounds__(256,1) k_gemm2() {
    extern __shared__ __nv_bfloat16 smg[];
    const int AS = 128*40;                  // elements per plane
    const uint32_t AS2 = AS*2;              // bytes
    int tid = threadIdx.x, lane = tid & 31, warp = tid >> 5;
    int co0 = blockIdx.x*128, bn0 = blockIdx.y*128;
    int wm = (warp >> 2)*64, wn = (warp & 3)*32;
    int g = lane >> 2, t4 = lane & 3;

    float acc[4][4][4];
    #pragma unroll
    for (int i = 0; i < 4; i++)
        #pragma unroll
        for (int j = 0; j < 4; j++)
            #pragma unroll
            for (int e = 0; e < 4; e++) acc[i][j][e] = 0.f;

    int r0 = tid >> 2, koff = (tid & 3)*8;
    const __nv_bfloat16* pAh = g_B2h + (size_t)(bn0 + r0)*KTOT + koff;
    const __nv_bfloat16* pAl = g_B2l + (size_t)(bn0 + r0)*KTOT + koff;
    const __nv_bfloat16* pWh = g_Wch + (size_t)(co0 + r0)*KTOT + koff;
    const __nv_bfloat16* pWl = g_Wcl + (size_t)(co0 + r0)*KTOT + koff;
    const size_t stepA = (size_t)64*KTOT;
    int so0 = r0*40 + koff, so1 = so0 + 64*40;

    uint32_t sbb = (uint32_t)__cvta_generic_to_shared(smg);
    int aRow = (lane & 7) + ((lane >> 3) & 1)*8;
    int aCol = (lane >> 4)*8;
    uint32_t aoff = ((wm + aRow)*40 + aCol)*2;
    int bRow = (lane & 7) + ((lane >> 4) & 1)*8;
    int bCol = ((lane >> 3) & 1)*8;
    uint32_t boff = ((wn + bRow)*40 + bCol)*2;

    const int NC = KTOT/32;
    uint4 rA[2], rAl[2], rW[2], rWl[2];

    rA[0]  = *(const uint4*)(pAh);  rA[1]  = *(const uint4*)(pAh + stepA);
    rAl[0] = *(const uint4*)(pAl);  rAl[1] = *(const uint4*)(pAl + stepA);
    rW[0]  = *(const uint4*)(pWh);  rW[1]  = *(const uint4*)(pWh + stepA);
    rWl[0] = *(const uint4*)(pWl);  rWl[1] = *(const uint4*)(pWl + stepA);
    {
        __nv_bfloat16* B = smg;
        *(uint4*)&B[0*AS + so0] = rA[0];  *(uint4*)&B[0*AS + so1] = rA[1];
        *(uint4*)&B[1*AS + so0] = rAl[0]; *(uint4*)&B[1*AS + so1] = rAl[1];
        *(uint4*)&B[2*AS + so0] = rW[0];  *(uint4*)&B[2*AS + so1] = rW[1];
        *(uint4*)&B[3*AS + so0] = rWl[0]; *(uint4*)&B[3*AS + so1] = rWl[1];
    }
    __syncthreads();

    for (int c = 0; c < NC; c++) {
        int buf = c & 1;
        if (c + 1 < NC) {
            int off = (c + 1)*32;
            rA[0]  = *(const uint4*)(pAh + off);  rA[1]  = *(const uint4*)(pAh + off + stepA);
            rAl[0] = *(const uint4*)(pAl + off);  rAl[1] = *(const uint4*)(pAl + off + stepA);
            rW[0]  = *(const uint4*)(pWh + off);  rW[1]  = *(const uint4*)(pWh + off + stepA);
            rWl[0] = *(const uint4*)(pWl + off);  rWl[1] = *(const uint4*)(pWl + off + stepA);
        }
        uint32_t bufB = sbb + buf*4*AS2;
        #pragma unroll
        for (int kq = 0; kq < 2; kq++) {
            uint32_t ah[4][4], al[4][4];
            #pragma unroll
            for (int mt = 0; mt < 4; mt++) {
                ldsm4(ah[mt], bufB + 0*AS2 + aoff + mt*1280 + kq*32);
                ldsm4(al[mt], bufB + 1*AS2 + aoff + mt*1280 + kq*32);
            }
            #pragma unroll
            for (int p = 0; p < 2; p++) {
                uint32_t bh[4], bl[4];
                ldsm4(bh, bufB + 2*AS2 + boff + p*1280 + kq*32);
                ldsm4(bl, bufB + 3*AS2 + boff + p*1280 + kq*32);
                #pragma unroll
                for (int mt = 0; mt < 4; mt++) {
                    mma16816(acc[mt][2*p],   ah[mt], bh[0], bh[1]);
                    mma16816(acc[mt][2*p],   ah[mt], bl[0], bl[1]);
                    mma16816(acc[mt][2*p],   al[mt], bh[0], bh[1]);
                    mma16816(acc[mt][2*p+1], ah[mt], bh[2], bh[3]);
                    mma16816(acc[mt][2*p+1], ah[mt], bl[2], bl[3]);
                    mma16816(acc[mt][2*p+1], al[mt], bh[2], bh[3]);
                }
            }
        }
        if (c + 1 < NC) {
            __nv_bfloat16* B = smg + (1 - buf)*4*AS;
            *(uint4*)&B[0*AS + so0] = rA[0];  *(uint4*)&B[0*AS + so1] = rA[1];
            *(uint4*)&B[1*AS + so0] = rAl[0]; *(uint4*)&B[1*AS + so1] = rAl[1];
            *(uint4*)&B[2*AS + so0] = rW[0];  *(uint4*)&B[2*AS + so1] = rW[1];
            *(uint4*)&B[3*AS + so0] = rWl[0]; *(uint4*)&B[3*AS + so1] = rWl[1];
        }
        __syncthreads();
    }

    #pragma unroll
    for (int mt = 0; mt < 4; mt++) {
        int row = bn0 + wm + mt*16 + g;
        #pragma unroll
        for (int nt = 0; nt < 4; nt++) {
            int col = co0 + wn + nt*8 + 2*t4;
            *(float2*)&g_O2[(size_t)row*NCO + col]       = make_float2(acc[mt][nt][0], acc[mt][nt][1]);
            *(float2*)&g_O2[(size_t)(row + 8)*NCO + col] = make_float2(acc[mt][nt][2], acc[mt][nt][3]);
        }
    }
}

// ---------------- BN2 stats + final relu/reshape ----------------
__global__ void k_stats2() {
    int sl = blockIdx.x, co = threadIdx.x;
    float s = 0.f, s2 = 0.f;
    for (int r = sl*64; r < sl*64 + 64; r++) {
        float v = g_O2[r*NCO + co]; s += v; s2 += v*v;
    }
    g_p2[sl*256 + co] = s; g_p3[sl*256 + co] = s2;
}

__global__ void k_fin2(const float* __restrict__ gma, const float* __restrict__ bta) {
    int co = threadIdx.x;
    float S = 0.f, S2 = 0.f;
    for (int s = 0; s < 256; s++) { S += g_p2[s*256 + co]; S2 += g_p3[s*256 + co]; }
    const float inv = 1.f/16384.f;
    float mean = S*inv;
    float var = S2*inv - mean*mean;
    float sc = gma[co]*rsqrtf(var + EPS);
    g_sc2[co] = sc; g_sh2[co] = bta[co] - mean*sc;
}

__global__ void k_out(float* __restrict__ out) {
    __shared__ float tile[32][257];
    int bn0 = blockIdx.x*32;
    int b = bn0 >> 11, n0 = bn0 & 2047;
    int tid = threadIdx.x;
    for (int i = tid; i < 32*256; i += 256) {
        int r = i >> 8, c = i & 255;
        tile[r][c] = g_O2[(bn0 + r)*NCO + c];
    }
    __syncthreads();
    for (int i = tid; i < 8192; i += 256) {
        int f = i >> 6, w = i & 63, half = w >> 5, nn = w & 31;
        int c = 2*f + half;
        float v = tile[nn][c]*g_sc2[c] + g_sh2[c];
        v = fmaxf(v, 0.f);
        out[((size_t)b*128 + f)*4096 + half*2048 + n0 + nn] = v;
    }
}

// ---------------- launch ----------------
extern "C" void kernel_launch(void* const* d_in, const int* in_sizes, int n_in,
                              void* d_out, int out_size) {
    const float* x  = (const float*)d_in[0];
    const float* w1 = (const float*)d_in[1];
    const float* g1 = (const float*)d_in[3];
    const float* b1 = (const float*)d_in[4];
    const float* w2 = (const float*)d_in[5];
    const float* g2 = (const float*)d_in[7];
    const float* b2 = (const float*)d_in[8];
    float* out = (float*)d_out;
    // conv biases are per-channel constants and cancel exactly under BN mean-subtraction.

    const int SM_GEMM2 = 2*4*128*40*2;   // 81920 B
    const int SM_UGEMM = 4*128*72*2;     // 73728 B
    cudaFuncSetAttribute(k_gemm2, cudaFuncAttributeMaxDynamicSharedMemorySize, SM_GEMM2);
    cudaFuncSetAttribute(k_ugemm, cudaFuncAttributeMaxDynamicSharedMemorySize, SM_UGEMM);

    k_prep_w1<<<768, 256>>>(w1);
    k_prep_wcat<<<dim3(16, 256), 256>>>(w2);
    k_transpose<<<dim3(64, 2, 8), dim3(32, 32)>>>(x);
    k_sq<<<2048, 256>>>();
    k_dist<<<dim3(528, 8), 256>>>();
    k_topk<<<16384, 256>>>();
    k_ugemm<<<dim3(16, 2, 96), 256, SM_UGEMM>>>();
    k_gather_nbx<<<16384, 256>>>();
    k_gather1<<<16384, 256>>>();
    k_red1<<<256, 256>>>();
    k_fin1<<<1, 256>>>(g1, b1);
    k_bnh<<<16384, 256>>>();
    k_gemm2<<<dim3(2, 128), 256, SM_GEMM2>>>();
    k_stats2<<<256, 256>>>();
    k_fin2<<<1, 256>>>(g2, b2);
    k_out<<<512, 256>>>(out);
}